// round 8
// baseline (speedup 1.0000x reference)
#include <cuda_runtime.h>
#include <cuda_fp16.h>
#include <stdint.h>

#define B 4
#define S 2048
#define H 8
#define E 64
#define BH (B*H)
#define PADQ 72   // Q/K smem row stride (halves)
#define PADT 72   // pv smem row stride (halves)

// ---------------------------------------------------------------------------
// Device scratch (allocation-free)
// ---------------------------------------------------------------------------
__device__ __half g_qh[(size_t)BH*S*E];   // fp16 hi of 0.125*Qproj [bh][s][e]
__device__ __half g_ql[(size_t)BH*S*E];
__device__ __half g_kh[(size_t)BH*S*E];   // [bh][s][e]
__device__ __half g_kl[(size_t)BH*S*E];
__device__ __half g_vh[(size_t)BH*E*S];   // transposed [bh][e][s]
__device__ __half g_vl[(size_t)BH*E*S];
__device__ __half g_p [(size_t)BH*S*S];   // fp16 p' = exp(s-m_t+ln512), even tiles masked
__device__ float  g_pm[(size_t)BH*16*32*128];  // per-tile row max
__device__ float  g_pl[(size_t)BH*16*32*128];  // per-tile partial l' (offset by 512x)

// ---------------------------------------------------------------------------
// MMA helpers (baseline PTX, works at .target sm_103)
// ---------------------------------------------------------------------------
__device__ __forceinline__ uint32_t smem_to_u32(const void* p) {
    uint32_t a;
    asm("{ .reg .u64 t; cvta.to.shared.u64 t, %1; cvt.u32.u64 %0, t; }" : "=r"(a) : "l"(p));
    return a;
}
#define LDSM_X4(R0, R1, R2, R3, ADDR) \
    asm volatile("ldmatrix.sync.aligned.m8n8.x4.shared.b16 {%0,%1,%2,%3}, [%4];" \
                 : "=r"(R0), "=r"(R1), "=r"(R2), "=r"(R3) : "r"(ADDR))
#define MMA16816(C, A0, A1, A2, A3, B0, B1) \
    asm volatile("mma.sync.aligned.m16n8k16.row.col.f32.f16.f16.f32 " \
                 "{%0,%1,%2,%3}, {%4,%5,%6,%7}, {%8,%9}, {%0,%1,%2,%3};" \
                 : "+f"((C)[0]), "+f"((C)[1]), "+f"((C)[2]), "+f"((C)[3]) \
                 : "r"(A0), "r"(A1), "r"(A2), "r"(A3), "r"(B0), "r"(B1))

// ---------------------------------------------------------------------------
// Threefry2x32 (JAX partitionable) — validated rounds 1-7
// ---------------------------------------------------------------------------
__device__ __forceinline__ uint32_t rotl32(uint32_t v, int s) { return __funnelshift_l(v, v, s); }
__device__ __forceinline__ uint32_t threefry_mask_bits(uint32_t idx) {
    const uint32_t ks0 = 0u, ks1 = 42u, ks2 = 0x1BD11BDAu ^ 42u;
    uint32_t x0 = ks0, x1 = idx + ks1;
#define TFR(r) { x0 += x1; x1 = rotl32(x1, r); x1 ^= x0; }
    TFR(13) TFR(15) TFR(26) TFR(6)
    x0 += ks1; x1 += ks2 + 1u;
    TFR(17) TFR(29) TFR(16) TFR(24)
    x0 += ks2; x1 += ks0 + 2u;
    TFR(13) TFR(15) TFR(26) TFR(6)
    x0 += ks0; x1 += ks1 + 3u;
    TFR(17) TFR(29) TFR(16) TFR(24)
    x0 += ks1; x1 += ks2 + 4u;
    TFR(13) TFR(15) TFR(26) TFR(6)
    x0 += ks2; x1 += ks0 + 5u;
#undef TFR
    return x0 ^ x1;
}
#define KEEP_THRESH (7549747u << 9)
#define C512 6.2383246250395075f   // ln(512): subnormal guard, cancels in normalization

// ---------------------------------------------------------------------------
// Kernel 1: QKV projection (round-6 version: register weight cache, 84us)
// ---------------------------------------------------------------------------
#define SYP 133

__global__ __launch_bounds__(256) void proj_kernel(
    const float* __restrict__ qin, const float* __restrict__ kin, const float* __restrict__ vin,
    const float* __restrict__ Wq, const float* __restrict__ bq,
    const float* __restrict__ Wk, const float* __restrict__ bk,
    const float* __restrict__ Wv, const float* __restrict__ bv)
{
    extern __shared__ char dyn[];
    float* sW = (float*)dyn;                 // [64][68]
    float* sbv = sW + 64 * 68;               // [64]
    float* sx = sbv + 64;                    // [128][64]
    uint32_t* sY = (uint32_t*)(sx + 128*64); // [64][SYP]  (V only)

    const int tid = threadIdx.x;
    const int s0 = blockIdx.x * 128;
    const int bh = blockIdx.y;
    const int m  = blockIdx.z;
    const int b = bh >> 3, h = bh & 7;

    const float* __restrict__ xin  = (m == 0) ? qin : ((m == 1) ? kin : vin);
    const float* __restrict__ W    = (m == 0) ? Wq  : ((m == 1) ? Wk  : Wv);
    const float* __restrict__ bias = (m == 0) ? bq  : ((m == 1) ? bk  : bv);

    for (int i = tid; i < 64 * 16; i += 256) {
        int r = i >> 4, c = i & 15;
        ((float4*)(sW + r * 68))[c] = ((const float4*)W)[i];
    }
    if (tid < 64) sbv[tid] = bias[tid];
    for (int i = tid; i < 128 * 16; i += 256) {
        int s = i >> 4, c = i & 15;
        ((float4*)(sx + s * 64))[c] =
            ((const float4*)(xin + ((size_t)((b * S + s0 + s) * H + h)) * 64))[c];
    }
    __syncthreads();

    const int f = tid & 63, sg = tid >> 6;

    float4 wr[16];
    #pragma unroll
    for (int e4 = 0; e4 < 16; e4++) wr[e4] = ((float4*)(sW + f * 68))[e4];
    const float bf = sbv[f];
    const float qs = (m == 0) ? 0.125f : 1.0f;

    if (m < 2) {
        __half* dh = ((m == 0) ? g_qh : g_kh) + ((size_t)bh * S + s0) * 64 + f;
        __half* dl = ((m == 0) ? g_ql : g_kl) + ((size_t)bh * S + s0) * 64 + f;
        #pragma unroll 4
        for (int ss = 0; ss < 32; ss++) {
            const int s = sg * 32 + ss;
            float acc = bf;
            #pragma unroll
            for (int e4 = 0; e4 < 16; e4++) {
                float4 xv = ((float4*)(sx + s * 64))[e4];
                acc += xv.x * wr[e4].x + xv.y * wr[e4].y + xv.z * wr[e4].z + xv.w * wr[e4].w;
            }
            acc *= qs;
            __half hi = __float2half_rn(acc);
            __half lo = __float2half_rn(acc - __half2float(hi));
            dh[(size_t)s * 64] = hi;
            dl[(size_t)s * 64] = lo;
        }
    } else {
        #pragma unroll 4
        for (int ss = 0; ss < 32; ss++) {
            const int s = sg * 32 + ss;
            float acc = bf;
            #pragma unroll
            for (int e4 = 0; e4 < 16; e4++) {
                float4 xv = ((float4*)(sx + s * 64))[e4];
                acc += xv.x * wr[e4].x + xv.y * wr[e4].y + xv.z * wr[e4].z + xv.w * wr[e4].w;
            }
            __half hi = __float2half_rn(acc);
            __half lo = __float2half_rn(acc - __half2float(hi));
            sY[f * SYP + s] = (uint32_t)__half_as_ushort(hi) |
                              ((uint32_t)__half_as_ushort(lo) << 16);
        }
        __syncthreads();
        for (int i = tid; i < 1024; i += 256) {
            const int fr = i >> 4, c = i & 15;
            const int sb8 = c * 8;
            uint32_t y[8];
            #pragma unroll
            for (int j = 0; j < 8; j++) y[j] = sY[fr * SYP + sb8 + j];
            uint4 hv, lv;
            hv.x = (y[0] & 0xffffu) | (y[1] << 16);
            hv.y = (y[2] & 0xffffu) | (y[3] << 16);
            hv.z = (y[4] & 0xffffu) | (y[5] << 16);
            hv.w = (y[6] & 0xffffu) | (y[7] << 16);
            lv.x = (y[0] >> 16) | (y[1] & 0xffff0000u);
            lv.y = (y[2] >> 16) | (y[3] & 0xffff0000u);
            lv.z = (y[4] >> 16) | (y[5] & 0xffff0000u);
            lv.w = (y[6] >> 16) | (y[7] & 0xffff0000u);
            const size_t off = ((size_t)bh * 64 + fr) * S + s0 + sb8;
            *(uint4*)(g_vh + off) = hv;
            *(uint4*)(g_vl + off) = lv;
        }
    }
}
#define PROJ_SMEM ((64*68 + 64 + 128*64) * 4 + 64 * SYP * 4)

// ---------------------------------------------------------------------------
// Kernel 2: scores (128q x 64k) -> p' fp16 spill + per-tile stats.
// Even-kc tiles: dropout applied in-place before store (half the threefry).
// ---------------------------------------------------------------------------
__global__ __launch_bounds__(256, 3) void scores_kernel()
{
    extern __shared__ char smraw[];
    __half* sQH = (__half*)smraw;             // [128][PADQ]
    __half* sQL = sQH + 128 * PADQ;
    __half* sKH = sQL + 128 * PADQ;           // [64][PADQ]
    __half* sKL = sKH + 64 * PADQ;
    float*  sP0 = (float*)(sKL + 64 * PADQ);  // [128]
    float*  sP1 = sP0 + 128;
    float*  sMr = sP1 + 128;

    const int tid = threadIdx.x;
    const int kc = blockIdx.x, qt = blockIdx.y, bh = blockIdx.z;
    const int k0 = kc * 64, q0 = qt * 128;

    const __half* qhp = g_qh + ((size_t)bh * S + q0) * 64;
    const __half* qlp = g_ql + ((size_t)bh * S + q0) * 64;
    const __half* khp = g_kh + ((size_t)bh * S + k0) * 64;
    const __half* klp = g_kl + ((size_t)bh * S + k0) * 64;

    for (int i = tid; i < 1024; i += 256) {
        int r = i >> 3, c = (i & 7) * 8;
        *(uint4*)(sQH + r * PADQ + c) = *(const uint4*)(qhp + r * 64 + c);
        *(uint4*)(sQL + r * PADQ + c) = *(const uint4*)(qlp + r * 64 + c);
    }
    for (int i = tid; i < 512; i += 256) {
        int r = i >> 3, c = (i & 7) * 8;
        *(uint4*)(sKH + r * PADQ + c) = *(const uint4*)(khp + r * 64 + c);
        *(uint4*)(sKL + r * PADQ + c) = *(const uint4*)(klp + r * 64 + c);
    }
    __syncthreads();

    const int w = tid >> 5, lane = tid & 31;
    const int qrow0 = (w >> 1) * 32, kcol0 = (w & 1) * 32;
    const int lr = lane & 7, lg = lane >> 3;
    const int er = lane >> 2, ec = (lane & 3) * 2;

    const int arow = qrow0 + lr + (lg & 1) * 8;
    const int acol = (lg >> 1) * 8;
    const int brow = kcol0 + lr + (lg >> 1) * 8;
    const int bcol = (lg & 1) * 8;

    const uint32_t uQH = smem_to_u32(sQH), uQL = smem_to_u32(sQL);
    const uint32_t uKH = smem_to_u32(sKH), uKL = smem_to_u32(sKL);

    float acc[2][4][4];
    #pragma unroll
    for (int i = 0; i < 2; i++)
        #pragma unroll
        for (int j = 0; j < 4; j++)
            #pragma unroll
            for (int l = 0; l < 4; l++) acc[i][j][l] = 0.0f;

    #pragma unroll
    for (int sp = 0; sp < 3; sp++) {
        const uint32_t uA = (sp < 2) ? uQH : uQL;
        const uint32_t uB = (sp == 1) ? uKL : uKH;
        #pragma unroll
        for (int ks = 0; ks < 4; ks++) {
            uint32_t a[2][4];
            #pragma unroll
            for (int mt = 0; mt < 2; mt++)
                LDSM_X4(a[mt][0], a[mt][1], a[mt][2], a[mt][3],
                        uA + (uint32_t)(((arow + mt * 16) * PADQ + acol + ks * 16) * 2));
            uint32_t bb[2][4];
            #pragma unroll
            for (int nbp = 0; nbp < 2; nbp++)
                LDSM_X4(bb[nbp][0], bb[nbp][1], bb[nbp][2], bb[nbp][3],
                        uB + (uint32_t)(((brow + nbp * 16) * PADQ + bcol + ks * 16) * 2));
            #pragma unroll
            for (int mt = 0; mt < 2; mt++)
                #pragma unroll
                for (int nb = 0; nb < 4; nb++)
                    MMA16816(acc[mt][nb], a[mt][0], a[mt][1], a[mt][2], a[mt][3],
                             bb[nb >> 1][(nb & 1) * 2], bb[nb >> 1][(nb & 1) * 2 + 1]);
        }
    }

    // ---- per-tile row max ----
    float rr2[2][2];
    #pragma unroll
    for (int mt = 0; mt < 2; mt++) {
        float m0 = -1e30f, m1 = -1e30f;
        #pragma unroll
        for (int nb = 0; nb < 4; nb++) {
            m0 = fmaxf(m0, fmaxf(acc[mt][nb][0], acc[mt][nb][1]));
            m1 = fmaxf(m1, fmaxf(acc[mt][nb][2], acc[mt][nb][3]));
        }
        m0 = fmaxf(m0, __shfl_xor_sync(0xffffffffu, m0, 1));
        m0 = fmaxf(m0, __shfl_xor_sync(0xffffffffu, m0, 2));
        m1 = fmaxf(m1, __shfl_xor_sync(0xffffffffu, m1, 1));
        m1 = fmaxf(m1, __shfl_xor_sync(0xffffffffu, m1, 2));
        rr2[mt][0] = m0; rr2[mt][1] = m1;
    }
    float* sP = (w & 1) ? sP1 : sP0;
    if ((lane & 3) == 0) {
        sP[qrow0 + er]      = rr2[0][0];
        sP[qrow0 + er + 8]  = rr2[0][1];
        sP[qrow0 + er + 16] = rr2[1][0];
        sP[qrow0 + er + 24] = rr2[1][1];
    }
    __syncthreads();
    if (tid < 128) sMr[tid] = fmaxf(sP0[tid], sP1[tid]);
    __syncthreads();

    // ---- rewrite acc -> p' = exp(s - m_t + ln512); partial l' ----
    float mrow[2][2];
    #pragma unroll
    for (int mt = 0; mt < 2; mt++) {
        mrow[mt][0] = sMr[qrow0 + mt * 16 + er];
        mrow[mt][1] = sMr[qrow0 + mt * 16 + er + 8];
    }
    #pragma unroll
    for (int mt = 0; mt < 2; mt++) {
        float s0 = 0.0f, s1 = 0.0f;
        #pragma unroll
        for (int nb = 0; nb < 4; nb++) {
            acc[mt][nb][0] = __expf(acc[mt][nb][0] - mrow[mt][0] + C512);
            acc[mt][nb][1] = __expf(acc[mt][nb][1] - mrow[mt][0] + C512);
            acc[mt][nb][2] = __expf(acc[mt][nb][2] - mrow[mt][1] + C512);
            acc[mt][nb][3] = __expf(acc[mt][nb][3] - mrow[mt][1] + C512);
            s0 += acc[mt][nb][0] + acc[mt][nb][1];
            s1 += acc[mt][nb][2] + acc[mt][nb][3];
        }
        s0 += __shfl_xor_sync(0xffffffffu, s0, 1);
        s0 += __shfl_xor_sync(0xffffffffu, s0, 2);
        s1 += __shfl_xor_sync(0xffffffffu, s1, 1);
        s1 += __shfl_xor_sync(0xffffffffu, s1, 2);
        rr2[mt][0] = s0; rr2[mt][1] = s1;
    }
    if ((lane & 3) == 0) {
        sP[qrow0 + er]      = rr2[0][0];
        sP[qrow0 + er + 8]  = rr2[0][1];
        sP[qrow0 + er + 16] = rr2[1][0];
        sP[qrow0 + er + 24] = rr2[1][1];
    }
    __syncthreads();
    if (tid < 128) {
        const size_t pidx = (((size_t)bh * 16 + qt) * 32 + kc) * 128 + tid;
        g_pm[pidx] = sMr[tid];
        g_pl[pidx] = sP0[tid] + sP1[tid];
    }

    // ---- dropout for EVEN tiles: zero dropped p' in-place ----
    if ((kc & 1) == 0) {
        #pragma unroll
        for (int mt = 0; mt < 2; mt++)
            #pragma unroll
            for (int roff = 0; roff < 2; roff++) {
                const int qg = q0 + qrow0 + mt * 16 + roff * 8 + er;
                const uint32_t idxbase =
                    (uint32_t)(bh * S + qg) * (uint32_t)S + (uint32_t)(k0 + kcol0 + ec);
                #pragma unroll
                for (int nb = 0; nb < 4; nb++) {
                    const uint32_t i0 = idxbase + nb * 8;
                    if (threefry_mask_bits(i0)      >= KEEP_THRESH) acc[mt][nb][roff*2+0] = 0.0f;
                    if (threefry_mask_bits(i0 + 1u) >= KEEP_THRESH) acc[mt][nb][roff*2+1] = 0.0f;
                }
            }
    }

    // ---- store p' fp16 ----
    __half* dst = g_p + ((size_t)bh * S + q0 + qrow0) * S + k0 + kcol0;
    #pragma unroll
    for (int mt = 0; mt < 2; mt++)
        #pragma unroll
        for (int nb = 0; nb < 4; nb++) {
            *(__half2*)(dst + (size_t)(mt * 16 + er) * S + nb * 8 + ec) =
                __floats2half2_rn(acc[mt][nb][0], acc[mt][nb][1]);
            *(__half2*)(dst + (size_t)(mt * 16 + er + 8) * S + nb * 8 + ec) =
                __floats2half2_rn(acc[mt][nb][2], acc[mt][nb][3]);
        }
}
#define SC_SMEM ((128*2 + 64*2) * PADQ * 2 + 3 * 128 * 4)

// ---------------------------------------------------------------------------
// Kernel 3: p'-load + corr-scale + odd-tile dropout + fp16 + PV.
// CTA: 64q x one bh; 64-wide chunks; 8 warps = 2(q) x 4(e).
// ---------------------------------------------------------------------------
__global__ __launch_bounds__(256, 3) void pv_kernel(float* __restrict__ out)
{
    extern __shared__ char smraw[];
    __half* sVH = (__half*)smraw;             // [64][PADT]
    __half* sVL = sVH + 64 * PADT;
    __half* sAT = sVL + 64 * PADT;            // [64][PADT]
    float*  sC  = (float*)(sAT + 64 * PADT);  // [32][64] corr per (tile,row)

    const int tid = threadIdx.x;
    const int q0 = blockIdx.x * 64, bh = blockIdx.y;

    // combine per-tile stats -> corr table
    if (tid < 64) {
        const int qt128 = q0 >> 7;
        const int r128 = (q0 & 127) + tid;
        const size_t pb = (((size_t)bh * 16 + qt128) * 32) * 128 + r128;
        float m = -1e30f;
        #pragma unroll 8
        for (int t = 0; t < 32; t++) m = fmaxf(m, g_pm[pb + t * 128]);
        float l = 0.0f;
        #pragma unroll 8
        for (int t = 0; t < 32; t++) l += g_pl[pb + t * 128] * __expf(g_pm[pb + t * 128] - m);
        const float inv = 1.0f / (0.9f * l);
        #pragma unroll 8
        for (int t = 0; t < 32; t++)
            sC[t * 64 + tid] = __expf(g_pm[pb + t * 128] - m) * inv;
    }
    __syncthreads();

    const int w = tid >> 5, lane = tid & 31;
    const int qrow0 = (w >> 2) * 32, ecol0 = (w & 3) * 16;
    const int lr = lane & 7, lg = lane >> 3;
    const int er = lane >> 2, ec = (lane & 3) * 2;

    const int arow = qrow0 + lr + (lg & 1) * 8;
    const int acol = (lg >> 1) * 8;
    const int brow = ecol0 + lr + (lg >> 1) * 8;
    const int bcol = (lg & 1) * 8;

    const uint32_t uVH = smem_to_u32(sVH), uVL = smem_to_u32(sVL);
    const uint32_t uAT = smem_to_u32(sAT);

    const __half* vhp = g_vh + (size_t)bh * 64 * S;
    const __half* vlp = g_vl + (size_t)bh * 64 * S;

    // softmax-stage mapping: 4 threads per row, 16 cols each
    const int row = tid >> 2;
    const int cb  = (tid & 3) * 16;
    const __half* prow = g_p + (size_t)(bh * S + q0 + row) * S;
    const uint32_t ib = (uint32_t)((bh * S + q0 + row) * S);

    float oacc[2][2][4];
    #pragma unroll
    for (int i = 0; i < 2; i++)
        #pragma unroll
        for (int j = 0; j < 2; j++)
            #pragma unroll
            for (int l = 0; l < 4; l++) oacc[i][j][l] = 0.0f;

    for (int c = 0; c < 32; c++) {
        // V chunk -> smem
        for (int i = tid; i < 512; i += 256) {
            int r = i >> 3, cc = (i & 7) * 8;
            *(uint4*)(sVH + r * PADT + cc) = *(const uint4*)(vhp + (size_t)r * S + c * 64 + cc);
            *(uint4*)(sVL + r * PADT + cc) = *(const uint4*)(vlp + (size_t)r * S + c * 64 + cc);
        }

        const int col0 = c * 64 + cb;
        const float corr = sC[c * 64 + row];

        uint4 pw0 = ((const uint4*)(prow + col0))[0];
        uint4 pw1 = ((const uint4*)(prow + col0))[1];
        const uint32_t pw[8] = {pw0.x, pw0.y, pw0.z, pw0.w, pw1.x, pw1.y, pw1.z, pw1.w};

        uint32_t keepbits = 0xffffffffu;
        if (c & 1) {
            keepbits = 0;
            #pragma unroll
            for (int j = 0; j < 16; j++)
                keepbits |= (threefry_mask_bits(ib + col0 + j) < KEEP_THRESH) ? (1u << j) : 0u;
        }

        uint32_t* dstw = (uint32_t*)(sAT + row * PADT + cb);
        #pragma unroll
        for (int jj = 0; jj < 8; jj++) {
            float2 f = __half22float2(*(const __half2*)&pw[jj]);
            float ta = f.x * corr;
            float tb = f.y * corr;
            ta = ((keepbits >> (jj * 2)) & 1u) ? ta : 0.0f;
            tb = ((keepbits >> (jj * 2 + 1)) & 1u) ? tb : 0.0f;
            dstw[jj] = (uint32_t)__half_as_ushort(__float2half_rn(ta)) |
                       ((uint32_t)__half_as_ushort(__float2half_rn(tb)) << 16);
        }
        __syncthreads();

        // PV MMA (warp tile 32q x 16e, k=64)
        #pragma unroll
        for (int ks = 0; ks < 4; ks++) {
            uint32_t a[2][4];
            #pragma unroll
            for (int mt = 0; mt < 2; mt++)
                LDSM_X4(a[mt][0], a[mt][1], a[mt][2], a[mt][3],
                        uAT + (uint32_t)(((arow + mt * 16) * PADT + acol + ks * 16) * 2));
            uint32_t bhf[4], blf[4];
            LDSM_X4(bhf[0], bhf[1], bhf[2], bhf[3],
                    uVH + (uint32_t)((brow * PADT + bcol + ks * 16) * 2));
            LDSM_X4(blf[0], blf[1], blf[2], blf[3],
                    uVL + (uint32_t)((brow * PADT + bcol + ks * 16) * 2));
            #pragma unroll
            for (int mt = 0; mt < 2; mt++)
                #pragma unroll
                for (int nb = 0; nb < 2; nb++) {
                    MMA16816(oacc[mt][nb], a[mt][0], a[mt][1], a[mt][2], a[mt][3],
                             bhf[nb * 2], bhf[nb * 2 + 1]);
                    MMA16816(oacc[mt][nb], a[mt][0], a[mt][1], a[mt][2], a[mt][3],
                             blf[nb * 2], blf[nb * 2 + 1]);
                }
        }
        __syncthreads();
    }

    float* dst = out + ((size_t)bh * S + q0 + qrow0) * 64 + ecol0;
    #pragma unroll
    for (int mt = 0; mt < 2; mt++)
        #pragma unroll
        for (int nb = 0; nb < 2; nb++) {
            *(float2*)(dst + (size_t)(mt * 16 + er) * 64 + nb * 8 + ec) =
                make_float2(oacc[mt][nb][0], oacc[mt][nb][1]);
            *(float2*)(dst + (size_t)(mt * 16 + er + 8) * 64 + nb * 8 + ec) =
                make_float2(oacc[mt][nb][2], oacc[mt][nb][3]);
        }
}
#define PV_SMEM (3 * 64 * PADT * 2 + 32 * 64 * 4)

// ---------------------------------------------------------------------------
extern "C" void kernel_launch(void* const* d_in, const int* in_sizes, int n_in,
                              void* d_out, int out_size) {
    (void)in_sizes; (void)n_in; (void)out_size;
    const float* query = (const float*)d_in[0];
    const float* key   = (const float*)d_in[1];
    const float* value = (const float*)d_in[2];
    const float* Wq    = (const float*)d_in[3];
    const float* bq    = (const float*)d_in[4];
    const float* Wk    = (const float*)d_in[5];
    const float* bk    = (const float*)d_in[6];
    const float* Wv    = (const float*)d_in[7];
    const float* bv    = (const float*)d_in[8];
    float* out = (float*)d_out;

    cudaFuncSetAttribute(proj_kernel,   cudaFuncAttributeMaxDynamicSharedMemorySize, PROJ_SMEM);
    cudaFuncSetAttribute(scores_kernel, cudaFuncAttributeMaxDynamicSharedMemorySize, SC_SMEM);
    cudaFuncSetAttribute(pv_kernel,     cudaFuncAttributeMaxDynamicSharedMemorySize, PV_SMEM);

    dim3 pg(S / 128, BH, 3);
    proj_kernel<<<pg, 256, PROJ_SMEM>>>(query, key, value, Wq, bq, Wk, bk, Wv, bv);

    dim3 sg(S / 64, S / 128, BH);
    scores_kernel<<<sg, 256, SC_SMEM>>>();

    dim3 ag(S / 64, BH);
    pv_kernel<<<ag, 256, PV_SMEM>>>(out);
}

// round 9
// speedup vs baseline: 1.0651x; 1.0651x over previous
#include <cuda_runtime.h>
#include <cuda_fp16.h>
#include <stdint.h>

#define B 4
#define S 2048
#define H 8
#define E 64
#define BH (B*H)
#define PADQ 72   // Q/K smem row stride (halves)
#define PADT 72   // pv smem row stride (halves)

// ---------------------------------------------------------------------------
// Device scratch (allocation-free)
// ---------------------------------------------------------------------------
__device__ __half g_qh[(size_t)BH*S*E];   // fp16 hi of 0.125*Qproj [bh][s][e]
__device__ __half g_ql[(size_t)BH*S*E];
__device__ __half g_kh[(size_t)BH*S*E];   // [bh][s][e]
__device__ __half g_kl[(size_t)BH*S*E];
__device__ __half g_vh[(size_t)BH*E*S];   // transposed [bh][e][s]
__device__ __half g_vl[(size_t)BH*E*S];
__device__ float  g_sc[(size_t)BH*S*S];   // raw fp32 scores [bh][q][k]
__device__ float  g_pm[(size_t)BH*16*32*128];  // per-tile row max   [bh][qt][kc64][r]
__device__ float  g_pl[(size_t)BH*16*32*128];  // per-tile partial l
__device__ uint32_t g_mask[(size_t)BH*S*64];   // keep-bits (even 64-tiles only)

// ---------------------------------------------------------------------------
// MMA helpers (baseline PTX, works at .target sm_103)
// ---------------------------------------------------------------------------
__device__ __forceinline__ uint32_t smem_to_u32(const void* p) {
    uint32_t a;
    asm("{ .reg .u64 t; cvta.to.shared.u64 t, %1; cvt.u32.u64 %0, t; }" : "=r"(a) : "l"(p));
    return a;
}
#define LDSM_X4(R0, R1, R2, R3, ADDR) \
    asm volatile("ldmatrix.sync.aligned.m8n8.x4.shared.b16 {%0,%1,%2,%3}, [%4];" \
                 : "=r"(R0), "=r"(R1), "=r"(R2), "=r"(R3) : "r"(ADDR))
#define MMA16816(C, A0, A1, A2, A3, B0, B1) \
    asm volatile("mma.sync.aligned.m16n8k16.row.col.f32.f16.f16.f32 " \
                 "{%0,%1,%2,%3}, {%4,%5,%6,%7}, {%8,%9}, {%0,%1,%2,%3};" \
                 : "+f"((C)[0]), "+f"((C)[1]), "+f"((C)[2]), "+f"((C)[3]) \
                 : "r"(A0), "r"(A1), "r"(A2), "r"(A3), "r"(B0), "r"(B1))

// ---------------------------------------------------------------------------
// Threefry2x32 (JAX partitionable) — validated rounds 1-8
// ---------------------------------------------------------------------------
__device__ __forceinline__ uint32_t rotl32(uint32_t v, int s) { return __funnelshift_l(v, v, s); }
__device__ __forceinline__ uint32_t threefry_mask_bits(uint32_t idx) {
    const uint32_t ks0 = 0u, ks1 = 42u, ks2 = 0x1BD11BDAu ^ 42u;
    uint32_t x0 = ks0, x1 = idx + ks1;
#define TFR(r) { x0 += x1; x1 = rotl32(x1, r); x1 ^= x0; }
    TFR(13) TFR(15) TFR(26) TFR(6)
    x0 += ks1; x1 += ks2 + 1u;
    TFR(17) TFR(29) TFR(16) TFR(24)
    x0 += ks2; x1 += ks0 + 2u;
    TFR(13) TFR(15) TFR(26) TFR(6)
    x0 += ks0; x1 += ks1 + 3u;
    TFR(17) TFR(29) TFR(16) TFR(24)
    x0 += ks1; x1 += ks2 + 4u;
    TFR(13) TFR(15) TFR(26) TFR(6)
    x0 += ks2; x1 += ks0 + 5u;
#undef TFR
    return x0 ^ x1;
}
#define KEEP_THRESH (7549747u << 9)

// ---------------------------------------------------------------------------
// Kernel 1: QKV projection (register weight cache; measured 83.5us)
// ---------------------------------------------------------------------------
#define SYP 133

__global__ __launch_bounds__(256) void proj_kernel(
    const float* __restrict__ qin, const float* __restrict__ kin, const float* __restrict__ vin,
    const float* __restrict__ Wq, const float* __restrict__ bq,
    const float* __restrict__ Wk, const float* __restrict__ bk,
    const float* __restrict__ Wv, const float* __restrict__ bv)
{
    extern __shared__ char dyn[];
    float* sW = (float*)dyn;                 // [64][68]
    float* sbv = sW + 64 * 68;               // [64]
    float* sx = sbv + 64;                    // [128][64]
    uint32_t* sY = (uint32_t*)(sx + 128*64); // [64][SYP]  (V only)

    const int tid = threadIdx.x;
    const int s0 = blockIdx.x * 128;
    const int bh = blockIdx.y;
    const int m  = blockIdx.z;
    const int b = bh >> 3, h = bh & 7;

    const float* __restrict__ xin  = (m == 0) ? qin : ((m == 1) ? kin : vin);
    const float* __restrict__ W    = (m == 0) ? Wq  : ((m == 1) ? Wk  : Wv);
    const float* __restrict__ bias = (m == 0) ? bq  : ((m == 1) ? bk  : bv);

    for (int i = tid; i < 64 * 16; i += 256) {
        int r = i >> 4, c = i & 15;
        ((float4*)(sW + r * 68))[c] = ((const float4*)W)[i];
    }
    if (tid < 64) sbv[tid] = bias[tid];
    for (int i = tid; i < 128 * 16; i += 256) {
        int s = i >> 4, c = i & 15;
        ((float4*)(sx + s * 64))[c] =
            ((const float4*)(xin + ((size_t)((b * S + s0 + s) * H + h)) * 64))[c];
    }
    __syncthreads();

    const int f = tid & 63, sg = tid >> 6;

    float4 wr[16];
    #pragma unroll
    for (int e4 = 0; e4 < 16; e4++) wr[e4] = ((float4*)(sW + f * 68))[e4];
    const float bf = sbv[f];
    const float qs = (m == 0) ? 0.125f : 1.0f;

    if (m < 2) {
        __half* dh = ((m == 0) ? g_qh : g_kh) + ((size_t)bh * S + s0) * 64 + f;
        __half* dl = ((m == 0) ? g_ql : g_kl) + ((size_t)bh * S + s0) * 64 + f;
        #pragma unroll 4
        for (int ss = 0; ss < 32; ss++) {
            const int s = sg * 32 + ss;
            float acc = bf;
            #pragma unroll
            for (int e4 = 0; e4 < 16; e4++) {
                float4 xv = ((float4*)(sx + s * 64))[e4];
                acc += xv.x * wr[e4].x + xv.y * wr[e4].y + xv.z * wr[e4].z + xv.w * wr[e4].w;
            }
            acc *= qs;
            __half hi = __float2half_rn(acc);
            __half lo = __float2half_rn(acc - __half2float(hi));
            dh[(size_t)s * 64] = hi;
            dl[(size_t)s * 64] = lo;
        }
    } else {
        #pragma unroll 4
        for (int ss = 0; ss < 32; ss++) {
            const int s = sg * 32 + ss;
            float acc = bf;
            #pragma unroll
            for (int e4 = 0; e4 < 16; e4++) {
                float4 xv = ((float4*)(sx + s * 64))[e4];
                acc += xv.x * wr[e4].x + xv.y * wr[e4].y + xv.z * wr[e4].z + xv.w * wr[e4].w;
            }
            __half hi = __float2half_rn(acc);
            __half lo = __float2half_rn(acc - __half2float(hi));
            sY[f * SYP + s] = (uint32_t)__half_as_ushort(hi) |
                              ((uint32_t)__half_as_ushort(lo) << 16);
        }
        __syncthreads();
        for (int i = tid; i < 1024; i += 256) {
            const int fr = i >> 4, c = i & 15;
            const int sb8 = c * 8;
            uint32_t y[8];
            #pragma unroll
            for (int j = 0; j < 8; j++) y[j] = sY[fr * SYP + sb8 + j];
            uint4 hv, lv;
            hv.x = (y[0] & 0xffffu) | (y[1] << 16);
            hv.y = (y[2] & 0xffffu) | (y[3] << 16);
            hv.z = (y[4] & 0xffffu) | (y[5] << 16);
            hv.w = (y[6] & 0xffffu) | (y[7] << 16);
            lv.x = (y[0] >> 16) | (y[1] & 0xffff0000u);
            lv.y = (y[2] >> 16) | (y[3] & 0xffff0000u);
            lv.z = (y[4] >> 16) | (y[5] & 0xffff0000u);
            lv.w = (y[6] >> 16) | (y[7] & 0xffff0000u);
            const size_t off = ((size_t)bh * 64 + fr) * S + s0 + sb8;
            *(uint4*)(g_vh + off) = hv;
            *(uint4*)(g_vl + off) = lv;
        }
    }
}
#define PROJ_SMEM ((64*68 + 64 + 128*64) * 4 + 64 * SYP * 4)

// ---------------------------------------------------------------------------
// Kernel 2: scores (128q x 64k tile) + per-tile stats + mask for EVEN tiles.
// (round-7 version, best measured)
// ---------------------------------------------------------------------------
__global__ __launch_bounds__(256, 3) void scores_kernel()
{
    extern __shared__ char smraw[];
    __half* sQH = (__half*)smraw;             // [128][PADQ]
    __half* sQL = sQH + 128 * PADQ;
    __half* sKH = sQL + 128 * PADQ;           // [64][PADQ]
    __half* sKL = sKH + 64 * PADQ;
    float*  sP0 = (float*)(sKL + 64 * PADQ);  // [128]
    float*  sP1 = sP0 + 128;
    float*  sMr = sP1 + 128;

    const int tid = threadIdx.x;
    const int kc = blockIdx.x, qt = blockIdx.y, bh = blockIdx.z;
    const int k0 = kc * 64, q0 = qt * 128;

    const __half* qhp = g_qh + ((size_t)bh * S + q0) * 64;
    const __half* qlp = g_ql + ((size_t)bh * S + q0) * 64;
    const __half* khp = g_kh + ((size_t)bh * S + k0) * 64;
    const __half* klp = g_kl + ((size_t)bh * S + k0) * 64;

    for (int i = tid; i < 1024; i += 256) {
        int r = i >> 3, c = (i & 7) * 8;
        *(uint4*)(sQH + r * PADQ + c) = *(const uint4*)(qhp + r * 64 + c);
        *(uint4*)(sQL + r * PADQ + c) = *(const uint4*)(qlp + r * 64 + c);
    }
    for (int i = tid; i < 512; i += 256) {
        int r = i >> 3, c = (i & 7) * 8;
        *(uint4*)(sKH + r * PADQ + c) = *(const uint4*)(khp + r * 64 + c);
        *(uint4*)(sKL + r * PADQ + c) = *(const uint4*)(klp + r * 64 + c);
    }
    __syncthreads();

    const int w = tid >> 5, lane = tid & 31;
    const int qrow0 = (w >> 1) * 32, kcol0 = (w & 1) * 32;
    const int lr = lane & 7, lg = lane >> 3;
    const int er = lane >> 2, ec = (lane & 3) * 2;

    const int arow = qrow0 + lr + (lg & 1) * 8;
    const int acol = (lg >> 1) * 8;
    const int brow = kcol0 + lr + (lg >> 1) * 8;
    const int bcol = (lg & 1) * 8;

    const uint32_t uQH = smem_to_u32(sQH), uQL = smem_to_u32(sQL);
    const uint32_t uKH = smem_to_u32(sKH), uKL = smem_to_u32(sKL);

    float acc[2][4][4];
    #pragma unroll
    for (int i = 0; i < 2; i++)
        #pragma unroll
        for (int j = 0; j < 4; j++)
            #pragma unroll
            for (int l = 0; l < 4; l++) acc[i][j][l] = 0.0f;

    #pragma unroll
    for (int sp = 0; sp < 3; sp++) {
        const uint32_t uA = (sp < 2) ? uQH : uQL;
        const uint32_t uB = (sp == 1) ? uKL : uKH;
        #pragma unroll
        for (int ks = 0; ks < 4; ks++) {
            uint32_t a[2][4];
            #pragma unroll
            for (int mt = 0; mt < 2; mt++)
                LDSM_X4(a[mt][0], a[mt][1], a[mt][2], a[mt][3],
                        uA + (uint32_t)(((arow + mt * 16) * PADQ + acol + ks * 16) * 2));
            uint32_t bb[2][4];
            #pragma unroll
            for (int nbp = 0; nbp < 2; nbp++)
                LDSM_X4(bb[nbp][0], bb[nbp][1], bb[nbp][2], bb[nbp][3],
                        uB + (uint32_t)(((brow + nbp * 16) * PADQ + bcol + ks * 16) * 2));
            #pragma unroll
            for (int mt = 0; mt < 2; mt++)
                #pragma unroll
                for (int nb = 0; nb < 4; nb++)
                    MMA16816(acc[mt][nb], a[mt][0], a[mt][1], a[mt][2], a[mt][3],
                             bb[nb >> 1][(nb & 1) * 2], bb[nb >> 1][(nb & 1) * 2 + 1]);
        }
    }

    // ---- dropout mask, EVEN tiles only ----
    if ((kc & 1) == 0) {
        const uint32_t kbase = (uint32_t)(k0 + kcol0 + ec);
        #pragma unroll
        for (int rr = 0; rr < 4; rr++) {
            const int qg = q0 + qrow0 + (rr >> 1) * 16 + (rr & 1) * 8 + er;
            const uint32_t idxbase = (uint32_t)(bh * S + qg) * (uint32_t)S + kbase;
            uint32_t w0 = 0;
            #pragma unroll
            for (int nb = 0; nb < 4; nb++) {
                const uint32_t i0 = idxbase + nb * 8;
                uint32_t bA = (threefry_mask_bits(i0) < KEEP_THRESH) ? 1u : 0u;
                uint32_t bB = (threefry_mask_bits(i0 + 1u) < KEEP_THRESH) ? 2u : 0u;
                w0 |= (bA | bB) << (nb * 8 + ec);
            }
            w0 |= __shfl_xor_sync(0xffffffffu, w0, 1);
            w0 |= __shfl_xor_sync(0xffffffffu, w0, 2);
            if ((lane & 3) == 0)
                g_mask[(size_t)(bh * S + qg) * 64 + kc * 2 + (kcol0 >> 5)] = w0;
        }
    }

    // ---- per-tile row max ----
    float rr2[2][2];
    #pragma unroll
    for (int mt = 0; mt < 2; mt++) {
        float m0 = -1e30f, m1 = -1e30f;
        #pragma unroll
        for (int nb = 0; nb < 4; nb++) {
            m0 = fmaxf(m0, fmaxf(acc[mt][nb][0], acc[mt][nb][1]));
            m1 = fmaxf(m1, fmaxf(acc[mt][nb][2], acc[mt][nb][3]));
        }
        m0 = fmaxf(m0, __shfl_xor_sync(0xffffffffu, m0, 1));
        m0 = fmaxf(m0, __shfl_xor_sync(0xffffffffu, m0, 2));
        m1 = fmaxf(m1, __shfl_xor_sync(0xffffffffu, m1, 1));
        m1 = fmaxf(m1, __shfl_xor_sync(0xffffffffu, m1, 2));
        rr2[mt][0] = m0; rr2[mt][1] = m1;
    }
    float* sP = (w & 1) ? sP1 : sP0;
    if ((lane & 3) == 0) {
        sP[qrow0 + er]      = rr2[0][0];
        sP[qrow0 + er + 8]  = rr2[0][1];
        sP[qrow0 + er + 16] = rr2[1][0];
        sP[qrow0 + er + 24] = rr2[1][1];
    }
    __syncthreads();
    if (tid < 128) sMr[tid] = fmaxf(sP0[tid], sP1[tid]);
    __syncthreads();

    // ---- per-tile partial l ----
    float mrow[2][2];
    #pragma unroll
    for (int mt = 0; mt < 2; mt++) {
        mrow[mt][0] = sMr[qrow0 + mt * 16 + er];
        mrow[mt][1] = sMr[qrow0 + mt * 16 + er + 8];
    }
    #pragma unroll
    for (int mt = 0; mt < 2; mt++) {
        float s0 = 0.0f, s1 = 0.0f;
        #pragma unroll
        for (int nb = 0; nb < 4; nb++) {
            s0 += __expf(acc[mt][nb][0] - mrow[mt][0]) + __expf(acc[mt][nb][1] - mrow[mt][0]);
            s1 += __expf(acc[mt][nb][2] - mrow[mt][1]) + __expf(acc[mt][nb][3] - mrow[mt][1]);
        }
        s0 += __shfl_xor_sync(0xffffffffu, s0, 1);
        s0 += __shfl_xor_sync(0xffffffffu, s0, 2);
        s1 += __shfl_xor_sync(0xffffffffu, s1, 1);
        s1 += __shfl_xor_sync(0xffffffffu, s1, 2);
        rr2[mt][0] = s0; rr2[mt][1] = s1;
    }
    if ((lane & 3) == 0) {
        sP[qrow0 + er]      = rr2[0][0];
        sP[qrow0 + er + 8]  = rr2[0][1];
        sP[qrow0 + er + 16] = rr2[1][0];
        sP[qrow0 + er + 24] = rr2[1][1];
    }
    __syncthreads();
    if (tid < 128) {
        const size_t pidx = (((size_t)bh * 16 + qt) * 32 + kc) * 128 + tid;
        g_pm[pidx] = sMr[tid];
        g_pl[pidx] = sP0[tid] + sP1[tid];
    }

    // ---- raw scores to gmem ----
    float* dst = g_sc + ((size_t)bh * S + q0 + qrow0) * S + k0 + kcol0;
    #pragma unroll
    for (int mt = 0; mt < 2; mt++)
        #pragma unroll
        for (int nb = 0; nb < 4; nb++) {
            *(float2*)(dst + (size_t)(mt * 16 + er) * S + nb * 8 + ec) =
                make_float2(acc[mt][nb][0], acc[mt][nb][1]);
            *(float2*)(dst + (size_t)(mt * 16 + er + 8) * S + nb * 8 + ec) =
                make_float2(acc[mt][nb][2], acc[mt][nb][3]);
        }
}
#define SC_SMEM ((128*2 + 64*2) * PADQ * 2 + 3 * 128 * 4)

// ---------------------------------------------------------------------------
// Kernel 3: softmax + dropout (half load / half compute) + fp16 + PV.
// (round-7 version, best measured)  occ 4.
// ---------------------------------------------------------------------------
__global__ __launch_bounds__(256, 4) void pv_kernel(float* __restrict__ out)
{
    extern __shared__ char smraw[];
    __half* sVH = (__half*)smraw;             // [64][PADT]
    __half* sVL = sVH + 64 * PADT;
    __half* sAT = sVL + 64 * PADT;            // [64][PADT]
    float*  sM  = (float*)(sAT + 64 * PADT);  // [64]
    float*  sInv = sM + 64;                   // [64]

    const int tid = threadIdx.x;
    const int q0 = blockIdx.x * 64, bh = blockIdx.y;

    if (tid < 64) {
        const int qt128 = q0 >> 7;
        const int r128 = (q0 & 127) + tid;
        const size_t pb = (((size_t)bh * 16 + qt128) * 32) * 128 + r128;
        float m = -1e30f;
        for (int t = 0; t < 32; t++) m = fmaxf(m, g_pm[pb + t * 128]);
        float l = 0.0f;
        for (int t = 0; t < 32; t++) l += g_pl[pb + t * 128] * __expf(g_pm[pb + t * 128] - m);
        sM[tid] = m;
        sInv[tid] = (1.0f / l) * (1.0f / 0.9f);
    }
    __syncthreads();

    const int w = tid >> 5, lane = tid & 31;
    const int qrow0 = (w >> 2) * 32, ecol0 = (w & 3) * 16;
    const int lr = lane & 7, lg = lane >> 3;
    const int er = lane >> 2, ec = (lane & 3) * 2;

    const int arow = qrow0 + lr + (lg & 1) * 8;
    const int acol = (lg >> 1) * 8;
    const int brow = ecol0 + lr + (lg >> 1) * 8;
    const int bcol = (lg & 1) * 8;

    const uint32_t uVH = smem_to_u32(sVH), uVL = smem_to_u32(sVL);
    const uint32_t uAT = smem_to_u32(sAT);

    const __half* vhp = g_vh + (size_t)bh * 64 * S;
    const __half* vlp = g_vl + (size_t)bh * 64 * S;

    const int row = tid >> 2;
    const int cb  = (tid & 3) * 16;
    const float mrow = sM[row], inv = sInv[row];
    const float* srow = g_sc + ((size_t)(bh * S + q0 + row)) * S;
    const uint32_t ib = (uint32_t)((bh * S + q0 + row) * S);
    const uint32_t* mrow_ptr = g_mask + (size_t)(bh * S + q0 + row) * 64;

    float oacc[2][2][4];
    #pragma unroll
    for (int i = 0; i < 2; i++)
        #pragma unroll
        for (int j = 0; j < 2; j++)
            #pragma unroll
            for (int l = 0; l < 4; l++) oacc[i][j][l] = 0.0f;

    for (int c = 0; c < 32; c++) {
        for (int i = tid; i < 512; i += 256) {
            int r = i >> 3, cc = (i & 7) * 8;
            *(uint4*)(sVH + r * PADT + cc) = *(const uint4*)(vhp + (size_t)r * S + c * 64 + cc);
            *(uint4*)(sVL + r * PADT + cc) = *(const uint4*)(vlp + (size_t)r * S + c * 64 + cc);
        }

        const int col0 = c * 64 + cb;
        float4 v[4];
        v[0] = *(const float4*)(srow + col0);
        v[1] = *(const float4*)(srow + col0 + 4);
        v[2] = *(const float4*)(srow + col0 + 8);
        v[3] = *(const float4*)(srow + col0 + 12);

        uint32_t keepbits;
        if ((c & 1) == 0) {
            keepbits = mrow_ptr[c * 2 + (cb >> 5)] >> (cb & 16);
        } else {
            keepbits = 0;
            #pragma unroll
            for (int j = 0; j < 16; j++)
                keepbits |= (threefry_mask_bits(ib + col0 + j) < KEEP_THRESH) ? (1u << j) : 0u;
        }

        uint32_t* dstw = (uint32_t*)(sAT + row * PADT + cb);
        #pragma unroll
        for (int jj = 0; jj < 8; jj++) {
            float sa = ((const float*)v)[jj * 2];
            float sb = ((const float*)v)[jj * 2 + 1];
            float ta = __expf(sa - mrow) * inv;
            float tb = __expf(sb - mrow) * inv;
            ta = ((keepbits >> (jj * 2)) & 1u) ? ta : 0.0f;
            tb = ((keepbits >> (jj * 2 + 1)) & 1u) ? tb : 0.0f;
            dstw[jj] = (uint32_t)__half_as_ushort(__float2half_rn(ta)) |
                       ((uint32_t)__half_as_ushort(__float2half_rn(tb)) << 16);
        }
        __syncthreads();

        #pragma unroll
        for (int ks = 0; ks < 4; ks++) {
            uint32_t a[2][4];
            #pragma unroll
            for (int mt = 0; mt < 2; mt++)
                LDSM_X4(a[mt][0], a[mt][1], a[mt][2], a[mt][3],
                        uAT + (uint32_t)(((arow + mt * 16) * PADT + acol + ks * 16) * 2));
            uint32_t bhf[4], blf[4];
            LDSM_X4(bhf[0], bhf[1], bhf[2], bhf[3],
                    uVH + (uint32_t)((brow * PADT + bcol + ks * 16) * 2));
            LDSM_X4(blf[0], blf[1], blf[2], blf[3],
                    uVL + (uint32_t)((brow * PADT + bcol + ks * 16) * 2));
            #pragma unroll
            for (int mt = 0; mt < 2; mt++)
                #pragma unroll
                for (int nb = 0; nb < 2; nb++) {
                    MMA16816(oacc[mt][nb], a[mt][0], a[mt][1], a[mt][2], a[mt][3],
                             bhf[nb * 2], bhf[nb * 2 + 1]);
                    MMA16816(oacc[mt][nb], a[mt][0], a[mt][1], a[mt][2], a[mt][3],
                             blf[nb * 2], blf[nb * 2 + 1]);
                }
        }
        __syncthreads();
    }

    float* dst = out + ((size_t)bh * S + q0 + qrow0) * 64 + ecol0;
    #pragma unroll
    for (int mt = 0; mt < 2; mt++)
        #pragma unroll
        for (int nb = 0; nb < 2; nb++) {
            *(float2*)(dst + (size_t)(mt * 16 + er) * 64 + nb * 8 + ec) =
                make_float2(oacc[mt][nb][0], oacc[mt][nb][1]);
            *(float2*)(dst + (size_t)(mt * 16 + er + 8) * 64 + nb * 8 + ec) =
                make_float2(oacc[mt][nb][2], oacc[mt][nb][3]);
        }
}
#define PV_SMEM (3 * 64 * PADT * 2 + 2 * 64 * 4)

// ---------------------------------------------------------------------------
extern "C" void kernel_launch(void* const* d_in, const int* in_sizes, int n_in,
                              void* d_out, int out_size) {
    (void)in_sizes; (void)n_in; (void)out_size;
    const float* query = (const float*)d_in[0];
    const float* key   = (const float*)d_in[1];
    const float* value = (const float*)d_in[2];
    const float* Wq    = (const float*)d_in[3];
    const float* bq    = (const float*)d_in[4];
    const float* Wk    = (const float*)d_in[5];
    const float* bk    = (const float*)d_in[6];
    const float* Wv    = (const float*)d_in[7];
    const float* bv    = (const float*)d_in[8];
    float* out = (float*)d_out;

    cudaFuncSetAttribute(proj_kernel,   cudaFuncAttributeMaxDynamicSharedMemorySize, PROJ_SMEM);
    cudaFuncSetAttribute(scores_kernel, cudaFuncAttributeMaxDynamicSharedMemorySize, SC_SMEM);
    cudaFuncSetAttribute(pv_kernel,     cudaFuncAttributeMaxDynamicSharedMemorySize, PV_SMEM);

    dim3 pg(S / 128, BH, 3);
    proj_kernel<<<pg, 256, PROJ_SMEM>>>(query, key, value, Wq, bq, Wk, bk, Wv, bv);

    dim3 sg(S / 64, S / 128, BH);
    scores_kernel<<<sg, 256, SC_SMEM>>>();

    dim3 ag(S / 64, BH);
    pv_kernel<<<ag, 256, PV_SMEM>>>(out);
}

// round 11
// speedup vs baseline: 1.1652x; 1.0940x over previous
#include <cuda_runtime.h>
#include <cuda_fp16.h>
#include <stdint.h>

#define B 4
#define S 2048
#define H 8
#define E 64
#define BH (B*H)
#define PADQ 72   // smem row stride (halves)
#define PADT 72

// ---------------------------------------------------------------------------
// Device scratch (allocation-free)
// ---------------------------------------------------------------------------
__device__ __half g_qh[(size_t)BH*S*E];
__device__ __half g_ql[(size_t)BH*S*E];
__device__ __half g_kh[(size_t)BH*S*E];
__device__ __half g_kl[(size_t)BH*S*E];
__device__ __half g_vh[(size_t)BH*E*S];   // transposed [bh][e][s]
__device__ __half g_vl[(size_t)BH*E*S];
__device__ float  g_sc[(size_t)BH*S*S];
__device__ float  g_pm[(size_t)BH*16*32*128];
__device__ float  g_pl[(size_t)BH*16*32*128];
__device__ uint32_t g_mask[(size_t)BH*S*64];

// ---------------------------------------------------------------------------
// MMA helpers
// ---------------------------------------------------------------------------
__device__ __forceinline__ uint32_t smem_to_u32(const void* p) {
    uint32_t a;
    asm("{ .reg .u64 t; cvta.to.shared.u64 t, %1; cvt.u32.u64 %0, t; }" : "=r"(a) : "l"(p));
    return a;
}
#define LDSM_X4(R0, R1, R2, R3, ADDR) \
    asm volatile("ldmatrix.sync.aligned.m8n8.x4.shared.b16 {%0,%1,%2,%3}, [%4];" \
                 : "=r"(R0), "=r"(R1), "=r"(R2), "=r"(R3) : "r"(ADDR))
#define MMA16816(C, A0, A1, A2, A3, B0, B1) \
    asm volatile("mma.sync.aligned.m16n8k16.row.col.f32.f16.f16.f32 " \
                 "{%0,%1,%2,%3}, {%4,%5,%6,%7}, {%8,%9}, {%0,%1,%2,%3};" \
                 : "+f"((C)[0]), "+f"((C)[1]), "+f"((C)[2]), "+f"((C)[3]) \
                 : "r"(A0), "r"(A1), "r"(A2), "r"(A3), "r"(B0), "r"(B1))

// ---------------------------------------------------------------------------
// Threefry2x32 (JAX partitionable) — validated rounds 1-9
// ---------------------------------------------------------------------------
__device__ __forceinline__ uint32_t rotl32(uint32_t v, int s) { return __funnelshift_l(v, v, s); }
__device__ __forceinline__ uint32_t threefry_mask_bits(uint32_t idx) {
    const uint32_t ks0 = 0u, ks1 = 42u, ks2 = 0x1BD11BDAu ^ 42u;
    uint32_t x0 = ks0, x1 = idx + ks1;
#define TFR(r) { x0 += x1; x1 = rotl32(x1, r); x1 ^= x0; }
    TFR(13) TFR(15) TFR(26) TFR(6)
    x0 += ks1; x1 += ks2 + 1u;
    TFR(17) TFR(29) TFR(16) TFR(24)
    x0 += ks2; x1 += ks0 + 2u;
    TFR(13) TFR(15) TFR(26) TFR(6)
    x0 += ks0; x1 += ks1 + 3u;
    TFR(17) TFR(29) TFR(16) TFR(24)
    x0 += ks1; x1 += ks2 + 4u;
    TFR(13) TFR(15) TFR(26) TFR(6)
    x0 += ks2; x1 += ks0 + 5u;
#undef TFR
    return x0 ^ x1;
}
#define KEEP_THRESH (7549747u << 9)

// ---------------------------------------------------------------------------
// Kernel 1: QKV projection via HMMA (hi/lo split of x and W, 3 products).
// CTA = 128 tokens of one (bh, m).  8 warps, warp tile 16tok x 64f.
// ---------------------------------------------------------------------------
#define PW 72
#define SYW 133   // V staging stride (uint32) — rows 0..127 (fixed from R10's 65)

__global__ __launch_bounds__(256, 3) void proj_kernel(
    const float* __restrict__ qin, const float* __restrict__ kin, const float* __restrict__ vin,
    const float* __restrict__ Wq, const float* __restrict__ bq,
    const float* __restrict__ Wk, const float* __restrict__ bk,
    const float* __restrict__ Wv, const float* __restrict__ bv)
{
    extern __shared__ char dyn[];
    __half* sWH = (__half*)dyn;               // [64][PW]
    __half* sWL = sWH + 64 * PW;
    __half* sXH = sWL + 64 * PW;              // [128][PW]
    __half* sXL = sXH + 128 * PW;
    float*  sbv = (float*)(sXL + 128 * PW);   // [64]
    uint32_t* sY = (uint32_t*)sXH;            // alias over sXH+sXL (V epilogue only)
                                              // 64*SYW*4 = 34048 B <= 36864 B

    const int tid = threadIdx.x;
    const int s0 = blockIdx.x * 128;
    const int bh = blockIdx.y;
    const int m  = blockIdx.z;
    const int b = bh >> 3, h = bh & 7;

    const float* __restrict__ xin  = (m == 0) ? qin : ((m == 1) ? kin : vin);
    const float* __restrict__ W    = (m == 0) ? Wq  : ((m == 1) ? Wk  : Wv);
    const float* __restrict__ bias = (m == 0) ? bq  : ((m == 1) ? bk  : bv);

    // W -> hi/lo smem (1024 float4s)
    for (int i = tid; i < 1024; i += 256) {
        int r = i >> 4, c4 = (i & 15) * 4;
        float4 wv = ((const float4*)W)[i];
        __half h0 = __float2half_rn(wv.x), h1 = __float2half_rn(wv.y);
        __half h2 = __float2half_rn(wv.z), h3 = __float2half_rn(wv.w);
        *(__half2*)(sWH + r * PW + c4)     = __halves2half2(h0, h1);
        *(__half2*)(sWH + r * PW + c4 + 2) = __halves2half2(h2, h3);
        *(__half2*)(sWL + r * PW + c4) = __halves2half2(
            __float2half_rn(wv.x - __half2float(h0)), __float2half_rn(wv.y - __half2float(h1)));
        *(__half2*)(sWL + r * PW + c4 + 2) = __halves2half2(
            __float2half_rn(wv.z - __half2float(h2)), __float2half_rn(wv.w - __half2float(h3)));
    }
    if (tid < 64) sbv[tid] = bias[tid];
    // X (128 tokens) -> hi/lo smem (2048 float4s)
    for (int i = tid; i < 2048; i += 256) {
        int r = i >> 4, c4 = (i & 15) * 4;
        float4 xv = ((const float4*)(xin + ((size_t)((b * S + s0 + r) * H + h)) * 64))[i & 15];
        __half h0 = __float2half_rn(xv.x), h1 = __float2half_rn(xv.y);
        __half h2 = __float2half_rn(xv.z), h3 = __float2half_rn(xv.w);
        *(__half2*)(sXH + r * PW + c4)     = __halves2half2(h0, h1);
        *(__half2*)(sXH + r * PW + c4 + 2) = __halves2half2(h2, h3);
        *(__half2*)(sXL + r * PW + c4) = __halves2half2(
            __float2half_rn(xv.x - __half2float(h0)), __float2half_rn(xv.y - __half2float(h1)));
        *(__half2*)(sXL + r * PW + c4 + 2) = __halves2half2(
            __float2half_rn(xv.z - __half2float(h2)), __float2half_rn(xv.w - __half2float(h3)));
    }
    __syncthreads();

    const int w = tid >> 5, lane = tid & 31;
    const int lr = lane & 7, lg = lane >> 3;
    const int er = lane >> 2, ec = (lane & 3) * 2;

    const int arow = w * 16 + lr + (lg & 1) * 8;   // A: X rows (tokens)
    const int acol = (lg >> 1) * 8;
    const int brow = lr + (lg >> 1) * 8;           // B: W rows (f) + nbp*16
    const int bcol = (lg & 1) * 8;

    const uint32_t uXH = smem_to_u32(sXH), uXL = smem_to_u32(sXL);
    const uint32_t uWH = smem_to_u32(sWH), uWL = smem_to_u32(sWL);

    float acc[8][4];
    #pragma unroll
    for (int j = 0; j < 8; j++)
        #pragma unroll
        for (int l = 0; l < 4; l++) acc[j][l] = 0.0f;

    #pragma unroll
    for (int ks = 0; ks < 4; ks++) {
        uint32_t aH[4], aL[4], bH[4][4], bL[4][4];
        LDSM_X4(aH[0], aH[1], aH[2], aH[3],
                uXH + (uint32_t)((arow * PW + acol + ks * 16) * 2));
        #pragma unroll
        for (int nbp = 0; nbp < 4; nbp++)
            LDSM_X4(bH[nbp][0], bH[nbp][1], bH[nbp][2], bH[nbp][3],
                    uWH + (uint32_t)(((brow + nbp * 16) * PW + bcol + ks * 16) * 2));
        #pragma unroll
        for (int nb = 0; nb < 8; nb++)
            MMA16816(acc[nb], aH[0], aH[1], aH[2], aH[3],
                     bH[nb >> 1][(nb & 1) * 2], bH[nb >> 1][(nb & 1) * 2 + 1]);
        #pragma unroll
        for (int nbp = 0; nbp < 4; nbp++)
            LDSM_X4(bL[nbp][0], bL[nbp][1], bL[nbp][2], bL[nbp][3],
                    uWL + (uint32_t)(((brow + nbp * 16) * PW + bcol + ks * 16) * 2));
        #pragma unroll
        for (int nb = 0; nb < 8; nb++)
            MMA16816(acc[nb], aH[0], aH[1], aH[2], aH[3],
                     bL[nb >> 1][(nb & 1) * 2], bL[nb >> 1][(nb & 1) * 2 + 1]);
        LDSM_X4(aL[0], aL[1], aL[2], aL[3],
                uXL + (uint32_t)((arow * PW + acol + ks * 16) * 2));
        #pragma unroll
        for (int nb = 0; nb < 8; nb++)
            MMA16816(acc[nb], aL[0], aL[1], aL[2], aL[3],
                     bH[nb >> 1][(nb & 1) * 2], bH[nb >> 1][(nb & 1) * 2 + 1]);
    }

    const float qs = (m == 0) ? 0.125f : 1.0f;
    const int row0 = w * 16 + er;     // token rows (local): row0, row0+8

    if (m < 2) {
        __half* dh = ((m == 0) ? g_qh : g_kh) + ((size_t)bh * S + s0) * 64;
        __half* dl = ((m == 0) ? g_ql : g_kl) + ((size_t)bh * S + s0) * 64;
        #pragma unroll
        for (int nb = 0; nb < 8; nb++) {
            const int col = nb * 8 + ec;
            const float b0 = sbv[col], b1 = sbv[col + 1];
            #pragma unroll
            for (int rr = 0; rr < 2; rr++) {
                const int row = row0 + rr * 8;
                float v0 = (acc[nb][rr * 2 + 0] + b0) * qs;
                float v1 = (acc[nb][rr * 2 + 1] + b1) * qs;
                __half h0 = __float2half_rn(v0), h1 = __float2half_rn(v1);
                *(__half2*)(dh + (size_t)row * 64 + col) = __halves2half2(h0, h1);
                *(__half2*)(dl + (size_t)row * 64 + col) = __halves2half2(
                    __float2half_rn(v0 - __half2float(h0)),
                    __float2half_rn(v1 - __half2float(h1)));
            }
        }
    } else {
        // V: stage packed hi|lo into sY[f][s] (aliased over sXH/sXL), then coalesced out
        __syncthreads();   // MMA reads of sXH/sXL complete before overwrite
        #pragma unroll
        for (int nb = 0; nb < 8; nb++) {
            const int col = nb * 8 + ec;
            const float b0 = sbv[col], b1 = sbv[col + 1];
            #pragma unroll
            for (int rr = 0; rr < 2; rr++) {
                const int row = row0 + rr * 8;
                float v0 = acc[nb][rr * 2 + 0] + b0;
                float v1 = acc[nb][rr * 2 + 1] + b1;
                __half h0 = __float2half_rn(v0), h1 = __float2half_rn(v1);
                __half l0 = __float2half_rn(v0 - __half2float(h0));
                __half l1 = __float2half_rn(v1 - __half2float(h1));
                sY[col * SYW + row] = (uint32_t)__half_as_ushort(h0) |
                                      ((uint32_t)__half_as_ushort(l0) << 16);
                sY[(col + 1) * SYW + row] = (uint32_t)__half_as_ushort(h1) |
                                            ((uint32_t)__half_as_ushort(l1) << 16);
            }
        }
        __syncthreads();
        for (int i = tid; i < 1024; i += 256) {
            const int fr = i >> 4, c = i & 15;
            const int sb8 = c * 8;
            uint32_t y[8];
            #pragma unroll
            for (int j = 0; j < 8; j++) y[j] = sY[fr * SYW + sb8 + j];
            uint4 hv, lv;
            hv.x = (y[0] & 0xffffu) | (y[1] << 16);
            hv.y = (y[2] & 0xffffu) | (y[3] << 16);
            hv.z = (y[4] & 0xffffu) | (y[5] << 16);
            hv.w = (y[6] & 0xffffu) | (y[7] << 16);
            lv.x = (y[0] >> 16) | (y[1] & 0xffff0000u);
            lv.y = (y[2] >> 16) | (y[3] & 0xffff0000u);
            lv.z = (y[4] >> 16) | (y[5] & 0xffff0000u);
            lv.w = (y[6] >> 16) | (y[7] & 0xffff0000u);
            const size_t off = ((size_t)bh * 64 + fr) * S + s0 + sb8;
            *(uint4*)(g_vh + off) = hv;
            *(uint4*)(g_vl + off) = lv;
        }
    }
}
#define PROJ_SMEM ((2*64*PW + 2*128*PW) * 2 + 64 * 4)

// ---------------------------------------------------------------------------
// Kernel 2: scores (128q x 64k) + stats + mask for EVEN tiles.
// Fragment-sharing ks loop (8 LDSM.x4/ks instead of 12).
// ---------------------------------------------------------------------------
__global__ __launch_bounds__(256, 3) void scores_kernel()
{
    extern __shared__ char smraw[];
    __half* sQH = (__half*)smraw;             // [128][PADQ]
    __half* sQL = sQH + 128 * PADQ;
    __half* sKH = sQL + 128 * PADQ;           // [64][PADQ]
    __half* sKL = sKH + 64 * PADQ;
    float*  sP0 = (float*)(sKL + 64 * PADQ);
    float*  sP1 = sP0 + 128;
    float*  sMr = sP1 + 128;

    const int tid = threadIdx.x;
    const int kc = blockIdx.x, qt = blockIdx.y, bh = blockIdx.z;
    const int k0 = kc * 64, q0 = qt * 128;

    const __half* qhp = g_qh + ((size_t)bh * S + q0) * 64;
    const __half* qlp = g_ql + ((size_t)bh * S + q0) * 64;
    const __half* khp = g_kh + ((size_t)bh * S + k0) * 64;
    const __half* klp = g_kl + ((size_t)bh * S + k0) * 64;

    for (int i = tid; i < 1024; i += 256) {
        int r = i >> 3, c = (i & 7) * 8;
        *(uint4*)(sQH + r * PADQ + c) = *(const uint4*)(qhp + r * 64 + c);
        *(uint4*)(sQL + r * PADQ + c) = *(const uint4*)(qlp + r * 64 + c);
    }
    for (int i = tid; i < 512; i += 256) {
        int r = i >> 3, c = (i & 7) * 8;
        *(uint4*)(sKH + r * PADQ + c) = *(const uint4*)(khp + r * 64 + c);
        *(uint4*)(sKL + r * PADQ + c) = *(const uint4*)(klp + r * 64 + c);
    }
    __syncthreads();

    const int w = tid >> 5, lane = tid & 31;
    const int qrow0 = (w >> 1) * 32, kcol0 = (w & 1) * 32;
    const int lr = lane & 7, lg = lane >> 3;
    const int er = lane >> 2, ec = (lane & 3) * 2;

    const int arow = qrow0 + lr + (lg & 1) * 8;
    const int acol = (lg >> 1) * 8;
    const int brow = kcol0 + lr + (lg >> 1) * 8;
    const int bcol = (lg & 1) * 8;

    const uint32_t uQH = smem_to_u32(sQH), uQL = smem_to_u32(sQL);
    const uint32_t uKH = smem_to_u32(sKH), uKL = smem_to_u32(sKL);

    float acc[2][4][4];
    #pragma unroll
    for (int i = 0; i < 2; i++)
        #pragma unroll
        for (int j = 0; j < 4; j++)
            #pragma unroll
            for (int l = 0; l < 4; l++) acc[i][j][l] = 0.0f;

    #pragma unroll
    for (int ks = 0; ks < 4; ks++) {
        uint32_t aH[2][4], aL[2][4], bH[2][4], bL[2][4];
        #pragma unroll
        for (int mt = 0; mt < 2; mt++)
            LDSM_X4(aH[mt][0], aH[mt][1], aH[mt][2], aH[mt][3],
                    uQH + (uint32_t)(((arow + mt * 16) * PADQ + acol + ks * 16) * 2));
        #pragma unroll
        for (int nbp = 0; nbp < 2; nbp++)
            LDSM_X4(bH[nbp][0], bH[nbp][1], bH[nbp][2], bH[nbp][3],
                    uKH + (uint32_t)(((brow + nbp * 16) * PADQ + bcol + ks * 16) * 2));
        #pragma unroll
        for (int mt = 0; mt < 2; mt++)
            #pragma unroll
            for (int nb = 0; nb < 4; nb++)
                MMA16816(acc[mt][nb], aH[mt][0], aH[mt][1], aH[mt][2], aH[mt][3],
                         bH[nb >> 1][(nb & 1) * 2], bH[nb >> 1][(nb & 1) * 2 + 1]);
        #pragma unroll
        for (int nbp = 0; nbp < 2; nbp++)
            LDSM_X4(bL[nbp][0], bL[nbp][1], bL[nbp][2], bL[nbp][3],
                    uKL + (uint32_t)(((brow + nbp * 16) * PADQ + bcol + ks * 16) * 2));
        #pragma unroll
        for (int mt = 0; mt < 2; mt++)
            #pragma unroll
            for (int nb = 0; nb < 4; nb++)
                MMA16816(acc[mt][nb], aH[mt][0], aH[mt][1], aH[mt][2], aH[mt][3],
                         bL[nb >> 1][(nb & 1) * 2], bL[nb >> 1][(nb & 1) * 2 + 1]);
        #pragma unroll
        for (int mt = 0; mt < 2; mt++)
            LDSM_X4(aL[mt][0], aL[mt][1], aL[mt][2], aL[mt][3],
                    uQL + (uint32_t)(((arow + mt * 16) * PADQ + acol + ks * 16) * 2));
        #pragma unroll
        for (int mt = 0; mt < 2; mt++)
            #pragma unroll
            for (int nb = 0; nb < 4; nb++)
                MMA16816(acc[mt][nb], aL[mt][0], aL[mt][1], aL[mt][2], aL[mt][3],
                         bH[nb >> 1][(nb & 1) * 2], bH[nb >> 1][(nb & 1) * 2 + 1]);
    }

    // ---- dropout mask, EVEN tiles only ----
    if ((kc & 1) == 0) {
        const uint32_t kbase = (uint32_t)(k0 + kcol0 + ec);
        #pragma unroll
        for (int rr = 0; rr < 4; rr++) {
            const int qg = q0 + qrow0 + (rr >> 1) * 16 + (rr & 1) * 8 + er;
            const uint32_t idxbase = (uint32_t)(bh * S + qg) * (uint32_t)S + kbase;
            uint32_t w0 = 0;
            #pragma unroll
            for (int nb = 0; nb < 4; nb++) {
                const uint32_t i0 = idxbase + nb * 8;
                uint32_t bA = (threefry_mask_bits(i0) < KEEP_THRESH) ? 1u : 0u;
                uint32_t bB = (threefry_mask_bits(i0 + 1u) < KEEP_THRESH) ? 2u : 0u;
                w0 |= (bA | bB) << (nb * 8 + ec);
            }
            w0 |= __shfl_xor_sync(0xffffffffu, w0, 1);
            w0 |= __shfl_xor_sync(0xffffffffu, w0, 2);
            if ((lane & 3) == 0)
                g_mask[(size_t)(bh * S + qg) * 64 + kc * 2 + (kcol0 >> 5)] = w0;
        }
    }

    // ---- per-tile row max ----
    float rr2[2][2];
    #pragma unroll
    for (int mt = 0; mt < 2; mt++) {
        float m0 = -1e30f, m1 = -1e30f;
        #pragma unroll
        for (int nb = 0; nb < 4; nb++) {
            m0 = fmaxf(m0, fmaxf(acc[mt][nb][0], acc[mt][nb][1]));
            m1 = fmaxf(m1, fmaxf(acc[mt][nb][2], acc[mt][nb][3]));
        }
        m0 = fmaxf(m0, __shfl_xor_sync(0xffffffffu, m0, 1));
        m0 = fmaxf(m0, __shfl_xor_sync(0xffffffffu, m0, 2));
        m1 = fmaxf(m1, __shfl_xor_sync(0xffffffffu, m1, 1));
        m1 = fmaxf(m1, __shfl_xor_sync(0xffffffffu, m1, 2));
        rr2[mt][0] = m0; rr2[mt][1] = m1;
    }
    float* sP = (w & 1) ? sP1 : sP0;
    if ((lane & 3) == 0) {
        sP[qrow0 + er]      = rr2[0][0];
        sP[qrow0 + er + 8]  = rr2[0][1];
        sP[qrow0 + er + 16] = rr2[1][0];
        sP[qrow0 + er + 24] = rr2[1][1];
    }
    __syncthreads();
    if (tid < 128) sMr[tid] = fmaxf(sP0[tid], sP1[tid]);
    __syncthreads();

    // ---- per-tile partial l ----
    float mrow[2][2];
    #pragma unroll
    for (int mt = 0; mt < 2; mt++) {
        mrow[mt][0] = sMr[qrow0 + mt * 16 + er];
        mrow[mt][1] = sMr[qrow0 + mt * 16 + er + 8];
    }
    #pragma unroll
    for (int mt = 0; mt < 2; mt++) {
        float s0 = 0.0f, s1 = 0.0f;
        #pragma unroll
        for (int nb = 0; nb < 4; nb++) {
            s0 += __expf(acc[mt][nb][0] - mrow[mt][0]) + __expf(acc[mt][nb][1] - mrow[mt][0]);
            s1 += __expf(acc[mt][nb][2] - mrow[mt][1]) + __expf(acc[mt][nb][3] - mrow[mt][1]);
        }
        s0 += __shfl_xor_sync(0xffffffffu, s0, 1);
        s0 += __shfl_xor_sync(0xffffffffu, s0, 2);
        s1 += __shfl_xor_sync(0xffffffffu, s1, 1);
        s1 += __shfl_xor_sync(0xffffffffu, s1, 2);
        rr2[mt][0] = s0; rr2[mt][1] = s1;
    }
    if ((lane & 3) == 0) {
        sP[qrow0 + er]      = rr2[0][0];
        sP[qrow0 + er + 8]  = rr2[0][1];
        sP[qrow0 + er + 16] = rr2[1][0];
        sP[qrow0 + er + 24] = rr2[1][1];
    }
    __syncthreads();
    if (tid < 128) {
        const size_t pidx = (((size_t)bh * 16 + qt) * 32 + kc) * 128 + tid;
        g_pm[pidx] = sMr[tid];
        g_pl[pidx] = sP0[tid] + sP1[tid];
    }

    // ---- raw scores to gmem ----
    float* dst = g_sc + ((size_t)bh * S + q0 + qrow0) * S + k0 + kcol0;
    #pragma unroll
    for (int mt = 0; mt < 2; mt++)
        #pragma unroll
        for (int nb = 0; nb < 4; nb++) {
            *(float2*)(dst + (size_t)(mt * 16 + er) * S + nb * 8 + ec) =
                make_float2(acc[mt][nb][0], acc[mt][nb][1]);
            *(float2*)(dst + (size_t)(mt * 16 + er + 8) * S + nb * 8 + ec) =
                make_float2(acc[mt][nb][2], acc[mt][nb][3]);
        }
}
#define SC_SMEM ((128*2 + 64*2) * PADQ * 2 + 3 * 128 * 4)

// ---------------------------------------------------------------------------
// Kernel 3: softmax + dropout (half load / half compute) + fp16 + PV.
// (round-9 version, best measured)
// ---------------------------------------------------------------------------
__global__ __launch_bounds__(256, 4) void pv_kernel(float* __restrict__ out)
{
    extern __shared__ char smraw[];
    __half* sVH = (__half*)smraw;
    __half* sVL = sVH + 64 * PADT;
    __half* sAT = sVL + 64 * PADT;
    float*  sM  = (float*)(sAT + 64 * PADT);
    float*  sInv = sM + 64;

    const int tid = threadIdx.x;
    const int q0 = blockIdx.x * 64, bh = blockIdx.y;

    if (tid < 64) {
        const int qt128 = q0 >> 7;
        const int r128 = (q0 & 127) + tid;
        const size_t pb = (((size_t)bh * 16 + qt128) * 32) * 128 + r128;
        float m = -1e30f;
        for (int t = 0; t < 32; t++) m = fmaxf(m, g_pm[pb + t * 128]);
        float l = 0.0f;
        for (int t = 0; t < 32; t++) l += g_pl[pb + t * 128] * __expf(g_pm[pb + t * 128] - m);
        sM[tid] = m;
        sInv[tid] = (1.0f / l) * (1.0f / 0.9f);
    }
    __syncthreads();

    const int w = tid >> 5, lane = tid & 31;
    const int qrow0 = (w >> 2) * 32, ecol0 = (w & 3) * 16;
    const int lr = lane & 7, lg = lane >> 3;
    const int er = lane >> 2, ec = (lane & 3) * 2;

    const int arow = qrow0 + lr + (lg & 1) * 8;
    const int acol = (lg >> 1) * 8;
    const int brow = ecol0 + lr + (lg >> 1) * 8;
    const int bcol = (lg & 1) * 8;

    const uint32_t uVH = smem_to_u32(sVH), uVL = smem_to_u32(sVL);
    const uint32_t uAT = smem_to_u32(sAT);

    const __half* vhp = g_vh + (size_t)bh * 64 * S;
    const __half* vlp = g_vl + (size_t)bh * 64 * S;

    const int row = tid >> 2;
    const int cb  = (tid & 3) * 16;
    const float mrow = sM[row], inv = sInv[row];
    const float* srow = g_sc + ((size_t)(bh * S + q0 + row)) * S;
    const uint32_t ib = (uint32_t)((bh * S + q0 + row) * S);
    const uint32_t* mrow_ptr = g_mask + (size_t)(bh * S + q0 + row) * 64;

    float oacc[2][2][4];
    #pragma unroll
    for (int i = 0; i < 2; i++)
        #pragma unroll
        for (int j = 0; j < 2; j++)
            #pragma unroll
            for (int l = 0; l < 4; l++) oacc[i][j][l] = 0.0f;

    for (int c = 0; c < 32; c++) {
        for (int i = tid; i < 512; i += 256) {
            int r = i >> 3, cc = (i & 7) * 8;
            *(uint4*)(sVH + r * PADT + cc) = *(const uint4*)(vhp + (size_t)r * S + c * 64 + cc);
            *(uint4*)(sVL + r * PADT + cc) = *(const uint4*)(vlp + (size_t)r * S + c * 64 + cc);
        }

        const int col0 = c * 64 + cb;
        float4 v[4];
        v[0] = *(const float4*)(srow + col0);
        v[1] = *(const float4*)(srow + col0 + 4);
        v[2] = *(const float4*)(srow + col0 + 8);
        v[3] = *(const float4*)(srow + col0 + 12);

        uint32_t keepbits;
        if ((c & 1) == 0) {
            keepbits = mrow_ptr[c * 2 + (cb >> 5)] >> (cb & 16);
        } else {
            keepbits = 0;
            #pragma unroll
            for (int j = 0; j < 16; j++)
                keepbits |= (threefry_mask_bits(ib + col0 + j) < KEEP_THRESH) ? (1u << j) : 0u;
        }

        uint32_t* dstw = (uint32_t*)(sAT + row * PADT + cb);
        #pragma unroll
        for (int jj = 0; jj < 8; jj++) {
            float sa = ((const float*)v)[jj * 2];
            float sb = ((const float*)v)[jj * 2 + 1];
            float ta = __expf(sa - mrow) * inv;
            float tb = __expf(sb - mrow) * inv;
            ta = ((keepbits >> (jj * 2)) & 1u) ? ta : 0.0f;
            tb = ((keepbits >> (jj * 2 + 1)) & 1u) ? tb : 0.0f;
            dstw[jj] = (uint32_t)__half_as_ushort(__float2half_rn(ta)) |
                       ((uint32_t)__half_as_ushort(__float2half_rn(tb)) << 16);
        }
        __syncthreads();

        #pragma unroll
        for (int ks = 0; ks < 4; ks++) {
            uint32_t a[2][4];
            #pragma unroll
            for (int mt = 0; mt < 2; mt++)
                LDSM_X4(a[mt][0], a[mt][1], a[mt][2], a[mt][3],
                        uAT + (uint32_t)(((arow + mt * 16) * PADT + acol + ks * 16) * 2));
            uint32_t bhf[4], blf[4];
            LDSM_X4(bhf[0], bhf[1], bhf[2], bhf[3],
                    uVH + (uint32_t)((brow * PADT + bcol + ks * 16) * 2));
            LDSM_X4(blf[0], blf[1], blf[2], blf[3],
                    uVL + (uint32_t)((brow * PADT + bcol + ks * 16) * 2));
            #pragma unroll
            for (int mt = 0; mt < 2; mt++)
                #pragma unroll
                for (int nb = 0; nb < 2; nb++) {
                    MMA16816(oacc[mt][nb], a[mt][0], a[mt][1], a[mt][2], a[mt][3],
                             bhf[nb * 2], bhf[nb * 2 + 1]);
                    MMA16816(oacc[mt][nb], a[mt][0], a[mt][1], a[mt][2], a[mt][3],
                             blf[nb * 2], blf[nb * 2 + 1]);
                }
        }
        __syncthreads();
    }

    float* dst = out + ((size_t)bh * S + q0 + qrow0) * 64 + ecol0;
    #pragma unroll
    for (int mt = 0; mt < 2; mt++)
        #pragma unroll
        for (int nb = 0; nb < 2; nb++) {
            *(float2*)(dst + (size_t)(mt * 16 + er) * 64 + nb * 8 + ec) =
                make_float2(oacc[mt][nb][0], oacc[mt][nb][1]);
            *(float2*)(dst + (size_t)(mt * 16 + er + 8) * 64 + nb * 8 + ec) =
                make_float2(oacc[mt][nb][2], oacc[mt][nb][3]);
        }
}
#define PV_SMEM (3 * 64 * PADT * 2 + 2 * 64 * 4)

// ---------------------------------------------------------------------------
extern "C" void kernel_launch(void* const* d_in, const int* in_sizes, int n_in,
                              void* d_out, int out_size) {
    (void)in_sizes; (void)n_in; (void)out_size;
    const float* query = (const float*)d_in[0];
    const float* key   = (const float*)d_in[1];
    const float* value = (const float*)d_in[2];
    const float* Wq    = (const float*)d_in[3];
    const float* bq    = (const float*)d_in[4];
    const float* Wk    = (const float*)d_in[5];
    const float* bk    = (const float*)d_in[6];
    const float* Wv    = (const float*)d_in[7];
    const float* bv    = (const float*)d_in[8];
    float* out = (float*)d_out;

    cudaFuncSetAttribute(proj_kernel,   cudaFuncAttributeMaxDynamicSharedMemorySize, PROJ_SMEM);
    cudaFuncSetAttribute(scores_kernel, cudaFuncAttributeMaxDynamicSharedMemorySize, SC_SMEM);
    cudaFuncSetAttribute(pv_kernel,     cudaFuncAttributeMaxDynamicSharedMemorySize, PV_SMEM);

    dim3 pg(S / 128, BH, 3);
    proj_kernel<<<pg, 256, PROJ_SMEM>>>(query, key, value, Wq, bq, Wk, bk, Wv, bv);

    dim3 sg(S / 64, S / 128, BH);
    scores_kernel<<<sg, 256, SC_SMEM>>>();

    dim3 ag(S / 64, BH);
    pv_kernel<<<ag, 256, PV_SMEM>>>(out);
}

// round 12
// speedup vs baseline: 1.1707x; 1.0047x over previous
#include <cuda_runtime.h>
#include <cuda_fp16.h>
#include <stdint.h>

#define B 4
#define S 2048
#define H 8
#define E 64
#define BH (B*H)
#define PADQ 72
#define PADT 72

// ---------------------------------------------------------------------------
// Device scratch (allocation-free)
// ---------------------------------------------------------------------------
__device__ __half g_qh[(size_t)BH*S*E];
__device__ __half g_ql[(size_t)BH*S*E];
__device__ __half g_kh[(size_t)BH*S*E];
__device__ __half g_kl[(size_t)BH*S*E];
__device__ __half g_vh[(size_t)BH*E*S];   // transposed [bh][e][s]
__device__ __half g_vl[(size_t)BH*E*S];
__device__ __half g_p [(size_t)BH*S*S];   // fp16 p' = exp(s-m_t+ln512), even tiles pre-masked
__device__ float  g_pm[(size_t)BH*16*32*128];
__device__ float  g_pl[(size_t)BH*16*32*128];

// ---------------------------------------------------------------------------
// MMA helpers
// ---------------------------------------------------------------------------
__device__ __forceinline__ uint32_t smem_to_u32(const void* p) {
    uint32_t a;
    asm("{ .reg .u64 t; cvta.to.shared.u64 t, %1; cvt.u32.u64 %0, t; }" : "=r"(a) : "l"(p));
    return a;
}
#define LDSM_X4(R0, R1, R2, R3, ADDR) \
    asm volatile("ldmatrix.sync.aligned.m8n8.x4.shared.b16 {%0,%1,%2,%3}, [%4];" \
                 : "=r"(R0), "=r"(R1), "=r"(R2), "=r"(R3) : "r"(ADDR))
#define MMA16816(C, A0, A1, A2, A3, B0, B1) \
    asm volatile("mma.sync.aligned.m16n8k16.row.col.f32.f16.f16.f32 " \
                 "{%0,%1,%2,%3}, {%4,%5,%6,%7}, {%8,%9}, {%0,%1,%2,%3};" \
                 : "+f"((C)[0]), "+f"((C)[1]), "+f"((C)[2]), "+f"((C)[3]) \
                 : "r"(A0), "r"(A1), "r"(A2), "r"(A3), "r"(B0), "r"(B1))

// ---------------------------------------------------------------------------
// Threefry2x32 (JAX partitionable) — validated rounds 1-11
// ---------------------------------------------------------------------------
__device__ __forceinline__ uint32_t rotl32(uint32_t v, int s) { return __funnelshift_l(v, v, s); }
__device__ __forceinline__ uint32_t threefry_mask_bits(uint32_t idx) {
    const uint32_t ks0 = 0u, ks1 = 42u, ks2 = 0x1BD11BDAu ^ 42u;
    uint32_t x0 = ks0, x1 = idx + ks1;
#define TFR(r) { x0 += x1; x1 = rotl32(x1, r); x1 ^= x0; }
    TFR(13) TFR(15) TFR(26) TFR(6)
    x0 += ks1; x1 += ks2 + 1u;
    TFR(17) TFR(29) TFR(16) TFR(24)
    x0 += ks2; x1 += ks0 + 2u;
    TFR(13) TFR(15) TFR(26) TFR(6)
    x0 += ks0; x1 += ks1 + 3u;
    TFR(17) TFR(29) TFR(16) TFR(24)
    x0 += ks1; x1 += ks2 + 4u;
    TFR(13) TFR(15) TFR(26) TFR(6)
    x0 += ks2; x1 += ks0 + 5u;
#undef TFR
    return x0 ^ x1;
}
#define KEEP_THRESH (7549747u << 9)
#define C512 6.2383246250395075f   // ln(512): fp16-subnormal guard, cancels in normalization

// ---------------------------------------------------------------------------
// Kernel 1: QKV projection via HMMA (round-11 version, measured 45us)
// ---------------------------------------------------------------------------
#define PW 72
#define SYW 133

__global__ __launch_bounds__(256, 3) void proj_kernel(
    const float* __restrict__ qin, const float* __restrict__ kin, const float* __restrict__ vin,
    const float* __restrict__ Wq, const float* __restrict__ bq,
    const float* __restrict__ Wk, const float* __restrict__ bk,
    const float* __restrict__ Wv, const float* __restrict__ bv)
{
    extern __shared__ char dyn[];
    __half* sWH = (__half*)dyn;               // [64][PW]
    __half* sWL = sWH + 64 * PW;
    __half* sXH = sWL + 64 * PW;              // [128][PW]
    __half* sXL = sXH + 128 * PW;
    float*  sbv = (float*)(sXL + 128 * PW);   // [64]
    uint32_t* sY = (uint32_t*)sXH;            // alias (V epilogue); 64*SYW*4 <= 36864

    const int tid = threadIdx.x;
    const int s0 = blockIdx.x * 128;
    const int bh = blockIdx.y;
    const int m  = blockIdx.z;
    const int b = bh >> 3, h = bh & 7;

    const float* __restrict__ xin  = (m == 0) ? qin : ((m == 1) ? kin : vin);
    const float* __restrict__ W    = (m == 0) ? Wq  : ((m == 1) ? Wk  : Wv);
    const float* __restrict__ bias = (m == 0) ? bq  : ((m == 1) ? bk  : bv);

    for (int i = tid; i < 1024; i += 256) {
        int r = i >> 4, c4 = (i & 15) * 4;
        float4 wv = ((const float4*)W)[i];
        __half h0 = __float2half_rn(wv.x), h1 = __float2half_rn(wv.y);
        __half h2 = __float2half_rn(wv.z), h3 = __float2half_rn(wv.w);
        *(__half2*)(sWH + r * PW + c4)     = __halves2half2(h0, h1);
        *(__half2*)(sWH + r * PW + c4 + 2) = __halves2half2(h2, h3);
        *(__half2*)(sWL + r * PW + c4) = __halves2half2(
            __float2half_rn(wv.x - __half2float(h0)), __float2half_rn(wv.y - __half2float(h1)));
        *(__half2*)(sWL + r * PW + c4 + 2) = __halves2half2(
            __float2half_rn(wv.z - __half2float(h2)), __float2half_rn(wv.w - __half2float(h3)));
    }
    if (tid < 64) sbv[tid] = bias[tid];
    for (int i = tid; i < 2048; i += 256) {
        int r = i >> 4, c4 = (i & 15) * 4;
        float4 xv = ((const float4*)(xin + ((size_t)((b * S + s0 + r) * H + h)) * 64))[i & 15];
        __half h0 = __float2half_rn(xv.x), h1 = __float2half_rn(xv.y);
        __half h2 = __float2half_rn(xv.z), h3 = __float2half_rn(xv.w);
        *(__half2*)(sXH + r * PW + c4)     = __halves2half2(h0, h1);
        *(__half2*)(sXH + r * PW + c4 + 2) = __halves2half2(h2, h3);
        *(__half2*)(sXL + r * PW + c4) = __halves2half2(
            __float2half_rn(xv.x - __half2float(h0)), __float2half_rn(xv.y - __half2float(h1)));
        *(__half2*)(sXL + r * PW + c4 + 2) = __halves2half2(
            __float2half_rn(xv.z - __half2float(h2)), __float2half_rn(xv.w - __half2float(h3)));
    }
    __syncthreads();

    const int w = tid >> 5, lane = tid & 31;
    const int lr = lane & 7, lg = lane >> 3;
    const int er = lane >> 2, ec = (lane & 3) * 2;

    const int arow = w * 16 + lr + (lg & 1) * 8;
    const int acol = (lg >> 1) * 8;
    const int brow = lr + (lg >> 1) * 8;
    const int bcol = (lg & 1) * 8;

    const uint32_t uXH = smem_to_u32(sXH), uXL = smem_to_u32(sXL);
    const uint32_t uWH = smem_to_u32(sWH), uWL = smem_to_u32(sWL);

    float acc[8][4];
    #pragma unroll
    for (int j = 0; j < 8; j++)
        #pragma unroll
        for (int l = 0; l < 4; l++) acc[j][l] = 0.0f;

    #pragma unroll
    for (int ks = 0; ks < 4; ks++) {
        uint32_t aH[4], aL[4], bH[4][4], bL[4][4];
        LDSM_X4(aH[0], aH[1], aH[2], aH[3],
                uXH + (uint32_t)((arow * PW + acol + ks * 16) * 2));
        #pragma unroll
        for (int nbp = 0; nbp < 4; nbp++)
            LDSM_X4(bH[nbp][0], bH[nbp][1], bH[nbp][2], bH[nbp][3],
                    uWH + (uint32_t)(((brow + nbp * 16) * PW + bcol + ks * 16) * 2));
        #pragma unroll
        for (int nb = 0; nb < 8; nb++)
            MMA16816(acc[nb], aH[0], aH[1], aH[2], aH[3],
                     bH[nb >> 1][(nb & 1) * 2], bH[nb >> 1][(nb & 1) * 2 + 1]);
        #pragma unroll
        for (int nbp = 0; nbp < 4; nbp++)
            LDSM_X4(bL[nbp][0], bL[nbp][1], bL[nbp][2], bL[nbp][3],
                    uWL + (uint32_t)(((brow + nbp * 16) * PW + bcol + ks * 16) * 2));
        #pragma unroll
        for (int nb = 0; nb < 8; nb++)
            MMA16816(acc[nb], aH[0], aH[1], aH[2], aH[3],
                     bL[nb >> 1][(nb & 1) * 2], bL[nb >> 1][(nb & 1) * 2 + 1]);
        LDSM_X4(aL[0], aL[1], aL[2], aL[3],
                uXL + (uint32_t)((arow * PW + acol + ks * 16) * 2));
        #pragma unroll
        for (int nb = 0; nb < 8; nb++)
            MMA16816(acc[nb], aL[0], aL[1], aL[2], aL[3],
                     bH[nb >> 1][(nb & 1) * 2], bH[nb >> 1][(nb & 1) * 2 + 1]);
    }

    const float qs = (m == 0) ? 0.125f : 1.0f;
    const int row0 = w * 16 + er;

    if (m < 2) {
        __half* dh = ((m == 0) ? g_qh : g_kh) + ((size_t)bh * S + s0) * 64;
        __half* dl = ((m == 0) ? g_ql : g_kl) + ((size_t)bh * S + s0) * 64;
        #pragma unroll
        for (int nb = 0; nb < 8; nb++) {
            const int col = nb * 8 + ec;
            const float b0 = sbv[col], b1 = sbv[col + 1];
            #pragma unroll
            for (int rr = 0; rr < 2; rr++) {
                const int row = row0 + rr * 8;
                float v0 = (acc[nb][rr * 2 + 0] + b0) * qs;
                float v1 = (acc[nb][rr * 2 + 1] + b1) * qs;
                __half h0 = __float2half_rn(v0), h1 = __float2half_rn(v1);
                *(__half2*)(dh + (size_t)row * 64 + col) = __halves2half2(h0, h1);
                *(__half2*)(dl + (size_t)row * 64 + col) = __halves2half2(
                    __float2half_rn(v0 - __half2float(h0)),
                    __float2half_rn(v1 - __half2float(h1)));
            }
        }
    } else {
        __syncthreads();
        #pragma unroll
        for (int nb = 0; nb < 8; nb++) {
            const int col = nb * 8 + ec;
            const float b0 = sbv[col], b1 = sbv[col + 1];
            #pragma unroll
            for (int rr = 0; rr < 2; rr++) {
                const int row = row0 + rr * 8;
                float v0 = acc[nb][rr * 2 + 0] + b0;
                float v1 = acc[nb][rr * 2 + 1] + b1;
                __half h0 = __float2half_rn(v0), h1 = __float2half_rn(v1);
                __half l0 = __float2half_rn(v0 - __half2float(h0));
                __half l1 = __float2half_rn(v1 - __half2float(h1));
                sY[col * SYW + row] = (uint32_t)__half_as_ushort(h0) |
                                      ((uint32_t)__half_as_ushort(l0) << 16);
                sY[(col + 1) * SYW + row] = (uint32_t)__half_as_ushort(h1) |
                                            ((uint32_t)__half_as_ushort(l1) << 16);
            }
        }
        __syncthreads();
        for (int i = tid; i < 1024; i += 256) {
            const int fr = i >> 4, c = i & 15;
            const int sb8 = c * 8;
            uint32_t y[8];
            #pragma unroll
            for (int j = 0; j < 8; j++) y[j] = sY[fr * SYW + sb8 + j];
            uint4 hv, lv;
            hv.x = (y[0] & 0xffffu) | (y[1] << 16);
            hv.y = (y[2] & 0xffffu) | (y[3] << 16);
            hv.z = (y[4] & 0xffffu) | (y[5] << 16);
            hv.w = (y[6] & 0xffffu) | (y[7] << 16);
            lv.x = (y[0] >> 16) | (y[1] & 0xffff0000u);
            lv.y = (y[2] >> 16) | (y[3] & 0xffff0000u);
            lv.z = (y[4] >> 16) | (y[5] & 0xffff0000u);
            lv.w = (y[6] >> 16) | (y[7] & 0xffff0000u);
            const size_t off = ((size_t)bh * 64 + fr) * S + s0 + sb8;
            *(uint4*)(g_vh + off) = hv;
            *(uint4*)(g_vl + off) = lv;
        }
    }
}
#define PROJ_SMEM ((2*64*PW + 2*128*PW) * 2 + 64 * 4)

// ---------------------------------------------------------------------------
// Kernel 2: scores (128q x 64k, r11 fast MMA) -> fp16 p' spill + stats.
// Even-kc tiles: dropout zeroed in-place before store.
// ---------------------------------------------------------------------------
__global__ __launch_bounds__(256, 3) void scores_kernel()
{
    extern __shared__ char smraw[];
    __half* sQH = (__half*)smraw;
    __half* sQL = sQH + 128 * PADQ;
    __half* sKH = sQL + 128 * PADQ;
    __half* sKL = sKH + 64 * PADQ;
    float*  sP0 = (float*)(sKL + 64 * PADQ);
    float*  sP1 = sP0 + 128;
    float*  sMr = sP1 + 128;

    const int tid = threadIdx.x;
    const int kc = blockIdx.x, qt = blockIdx.y, bh = blockIdx.z;
    const int k0 = kc * 64, q0 = qt * 128;

    const __half* qhp = g_qh + ((size_t)bh * S + q0) * 64;
    const __half* qlp = g_ql + ((size_t)bh * S + q0) * 64;
    const __half* khp = g_kh + ((size_t)bh * S + k0) * 64;
    const __half* klp = g_kl + ((size_t)bh * S + k0) * 64;

    for (int i = tid; i < 1024; i += 256) {
        int r = i >> 3, c = (i & 7) * 8;
        *(uint4*)(sQH + r * PADQ + c) = *(const uint4*)(qhp + r * 64 + c);
        *(uint4*)(sQL + r * PADQ + c) = *(const uint4*)(qlp + r * 64 + c);
    }
    for (int i = tid; i < 512; i += 256) {
        int r = i >> 3, c = (i & 7) * 8;
        *(uint4*)(sKH + r * PADQ + c) = *(const uint4*)(khp + r * 64 + c);
        *(uint4*)(sKL + r * PADQ + c) = *(const uint4*)(klp + r * 64 + c);
    }
    __syncthreads();

    const int w = tid >> 5, lane = tid & 31;
    const int qrow0 = (w >> 1) * 32, kcol0 = (w & 1) * 32;
    const int lr = lane & 7, lg = lane >> 3;
    const int er = lane >> 2, ec = (lane & 3) * 2;

    const int arow = qrow0 + lr + (lg & 1) * 8;
    const int acol = (lg >> 1) * 8;
    const int brow = kcol0 + lr + (lg >> 1) * 8;
    const int bcol = (lg & 1) * 8;

    const uint32_t uQH = smem_to_u32(sQH), uQL = smem_to_u32(sQL);
    const uint32_t uKH = smem_to_u32(sKH), uKL = smem_to_u32(sKL);

    float acc[2][4][4];
    #pragma unroll
    for (int i = 0; i < 2; i++)
        #pragma unroll
        for (int j = 0; j < 4; j++)
            #pragma unroll
            for (int l = 0; l < 4; l++) acc[i][j][l] = 0.0f;

    #pragma unroll
    for (int ks = 0; ks < 4; ks++) {
        uint32_t aH[2][4], aL[2][4], bH[2][4], bL[2][4];
        #pragma unroll
        for (int mt = 0; mt < 2; mt++)
            LDSM_X4(aH[mt][0], aH[mt][1], aH[mt][2], aH[mt][3],
                    uQH + (uint32_t)(((arow + mt * 16) * PADQ + acol + ks * 16) * 2));
        #pragma unroll
        for (int nbp = 0; nbp < 2; nbp++)
            LDSM_X4(bH[nbp][0], bH[nbp][1], bH[nbp][2], bH[nbp][3],
                    uKH + (uint32_t)(((brow + nbp * 16) * PADQ + bcol + ks * 16) * 2));
        #pragma unroll
        for (int mt = 0; mt < 2; mt++)
            #pragma unroll
            for (int nb = 0; nb < 4; nb++)
                MMA16816(acc[mt][nb], aH[mt][0], aH[mt][1], aH[mt][2], aH[mt][3],
                         bH[nb >> 1][(nb & 1) * 2], bH[nb >> 1][(nb & 1) * 2 + 1]);
        #pragma unroll
        for (int nbp = 0; nbp < 2; nbp++)
            LDSM_X4(bL[nbp][0], bL[nbp][1], bL[nbp][2], bL[nbp][3],
                    uKL + (uint32_t)(((brow + nbp * 16) * PADQ + bcol + ks * 16) * 2));
        #pragma unroll
        for (int mt = 0; mt < 2; mt++)
            #pragma unroll
            for (int nb = 0; nb < 4; nb++)
                MMA16816(acc[mt][nb], aH[mt][0], aH[mt][1], aH[mt][2], aH[mt][3],
                         bL[nb >> 1][(nb & 1) * 2], bL[nb >> 1][(nb & 1) * 2 + 1]);
        #pragma unroll
        for (int mt = 0; mt < 2; mt++)
            LDSM_X4(aL[mt][0], aL[mt][1], aL[mt][2], aL[mt][3],
                    uQL + (uint32_t)(((arow + mt * 16) * PADQ + acol + ks * 16) * 2));
        #pragma unroll
        for (int mt = 0; mt < 2; mt++)
            #pragma unroll
            for (int nb = 0; nb < 4; nb++)
                MMA16816(acc[mt][nb], aL[mt][0], aL[mt][1], aL[mt][2], aL[mt][3],
                         bH[nb >> 1][(nb & 1) * 2], bH[nb >> 1][(nb & 1) * 2 + 1]);
    }

    // ---- per-tile row max ----
    float rr2[2][2];
    #pragma unroll
    for (int mt = 0; mt < 2; mt++) {
        float m0 = -1e30f, m1 = -1e30f;
        #pragma unroll
        for (int nb = 0; nb < 4; nb++) {
            m0 = fmaxf(m0, fmaxf(acc[mt][nb][0], acc[mt][nb][1]));
            m1 = fmaxf(m1, fmaxf(acc[mt][nb][2], acc[mt][nb][3]));
        }
        m0 = fmaxf(m0, __shfl_xor_sync(0xffffffffu, m0, 1));
        m0 = fmaxf(m0, __shfl_xor_sync(0xffffffffu, m0, 2));
        m1 = fmaxf(m1, __shfl_xor_sync(0xffffffffu, m1, 1));
        m1 = fmaxf(m1, __shfl_xor_sync(0xffffffffu, m1, 2));
        rr2[mt][0] = m0; rr2[mt][1] = m1;
    }
    float* sP = (w & 1) ? sP1 : sP0;
    if ((lane & 3) == 0) {
        sP[qrow0 + er]      = rr2[0][0];
        sP[qrow0 + er + 8]  = rr2[0][1];
        sP[qrow0 + er + 16] = rr2[1][0];
        sP[qrow0 + er + 24] = rr2[1][1];
    }
    __syncthreads();
    if (tid < 128) sMr[tid] = fmaxf(sP0[tid], sP1[tid]);
    __syncthreads();

    // ---- acc -> p' = exp(s - m_t + ln512); partial l' ----
    float mrow[2][2];
    #pragma unroll
    for (int mt = 0; mt < 2; mt++) {
        mrow[mt][0] = sMr[qrow0 + mt * 16 + er];
        mrow[mt][1] = sMr[qrow0 + mt * 16 + er + 8];
    }
    #pragma unroll
    for (int mt = 0; mt < 2; mt++) {
        float s0 = 0.0f, s1 = 0.0f;
        #pragma unroll
        for (int nb = 0; nb < 4; nb++) {
            acc[mt][nb][0] = __expf(acc[mt][nb][0] - mrow[mt][0] + C512);
            acc[mt][nb][1] = __expf(acc[mt][nb][1] - mrow[mt][0] + C512);
            acc[mt][nb][2] = __expf(acc[mt][nb][2] - mrow[mt][1] + C512);
            acc[mt][nb][3] = __expf(acc[mt][nb][3] - mrow[mt][1] + C512);
            s0 += acc[mt][nb][0] + acc[mt][nb][1];
            s1 += acc[mt][nb][2] + acc[mt][nb][3];
        }
        s0 += __shfl_xor_sync(0xffffffffu, s0, 1);
        s0 += __shfl_xor_sync(0xffffffffu, s0, 2);
        s1 += __shfl_xor_sync(0xffffffffu, s1, 1);
        s1 += __shfl_xor_sync(0xffffffffu, s1, 2);
        rr2[mt][0] = s0; rr2[mt][1] = s1;
    }
    if ((lane & 3) == 0) {
        sP[qrow0 + er]      = rr2[0][0];
        sP[qrow0 + er + 8]  = rr2[0][1];
        sP[qrow0 + er + 16] = rr2[1][0];
        sP[qrow0 + er + 24] = rr2[1][1];
    }
    __syncthreads();
    if (tid < 128) {
        const size_t pidx = (((size_t)bh * 16 + qt) * 32 + kc) * 128 + tid;
        g_pm[pidx] = sMr[tid];
        g_pl[pidx] = sP0[tid] + sP1[tid];
    }

    // ---- dropout for EVEN tiles: zero dropped p' in place (no mask store) ----
    if ((kc & 1) == 0) {
        #pragma unroll
        for (int mt = 0; mt < 2; mt++)
            #pragma unroll
            for (int roff = 0; roff < 2; roff++) {
                const int qg = q0 + qrow0 + mt * 16 + roff * 8 + er;
                const uint32_t idxbase =
                    (uint32_t)(bh * S + qg) * (uint32_t)S + (uint32_t)(k0 + kcol0 + ec);
                #pragma unroll
                for (int nb = 0; nb < 4; nb++) {
                    const uint32_t i0 = idxbase + nb * 8;
                    if (threefry_mask_bits(i0)      >= KEEP_THRESH) acc[mt][nb][roff*2+0] = 0.0f;
                    if (threefry_mask_bits(i0 + 1u) >= KEEP_THRESH) acc[mt][nb][roff*2+1] = 0.0f;
                }
            }
    }

    // ---- store p' fp16 ----
    __half* dst = g_p + ((size_t)bh * S + q0 + qrow0) * S + k0 + kcol0;
    #pragma unroll
    for (int mt = 0; mt < 2; mt++)
        #pragma unroll
        for (int nb = 0; nb < 4; nb++) {
            *(__half2*)(dst + (size_t)(mt * 16 + er) * S + nb * 8 + ec) =
                __floats2half2_rn(acc[mt][nb][0], acc[mt][nb][1]);
            *(__half2*)(dst + (size_t)(mt * 16 + er + 8) * S + nb * 8 + ec) =
                __floats2half2_rn(acc[mt][nb][2], acc[mt][nb][3]);
        }
}
#define SC_SMEM ((128*2 + 64*2) * PADQ * 2 + 3 * 128 * 4)

// ---------------------------------------------------------------------------
// Kernel 3: p'-load + corr-scale + odd-tile dropout + fp16 + PV.  occ 4.
// CTA: 64q x one bh; 64-wide chunks; 8 warps = 2(q) x 4(e).
// ---------------------------------------------------------------------------
__global__ __launch_bounds__(256, 4) void pv_kernel(float* __restrict__ out)
{
    extern __shared__ char smraw[];
    __half* sVH = (__half*)smraw;             // [64][PADT]
    __half* sVL = sVH + 64 * PADT;
    __half* sAT = sVL + 64 * PADT;            // [64][PADT]
    float*  sC  = (float*)(sAT + 64 * PADT);  // [32][64] corr per (tile,row)

    const int tid = threadIdx.x;
    const int q0 = blockIdx.x * 64, bh = blockIdx.y;

    if (tid < 64) {
        const int qt128 = q0 >> 7;
        const int r128 = (q0 & 127) + tid;
        const size_t pb = (((size_t)bh * 16 + qt128) * 32) * 128 + r128;
        float m = -1e30f;
        #pragma unroll 8
        for (int t = 0; t < 32; t++) m = fmaxf(m, g_pm[pb + t * 128]);
        float l = 0.0f;
        #pragma unroll 8
        for (int t = 0; t < 32; t++) l += g_pl[pb + t * 128] * __expf(g_pm[pb + t * 128] - m);
        const float inv = 1.0f / (0.9f * l);
        #pragma unroll 8
        for (int t = 0; t < 32; t++)
            sC[t * 64 + tid] = __expf(g_pm[pb + t * 128] - m) * inv;
    }
    __syncthreads();

    const int w = tid >> 5, lane = tid & 31;
    const int qrow0 = (w >> 2) * 32, ecol0 = (w & 3) * 16;
    const int lr = lane & 7, lg = lane >> 3;
    const int er = lane >> 2, ec = (lane & 3) * 2;

    const int arow = qrow0 + lr + (lg & 1) * 8;
    const int acol = (lg >> 1) * 8;
    const int brow = ecol0 + lr + (lg >> 1) * 8;
    const int bcol = (lg & 1) * 8;

    const uint32_t uVH = smem_to_u32(sVH), uVL = smem_to_u32(sVL);
    const uint32_t uAT = smem_to_u32(sAT);

    const __half* vhp = g_vh + (size_t)bh * 64 * S;
    const __half* vlp = g_vl + (size_t)bh * 64 * S;

    const int row = tid >> 2;
    const int cb  = (tid & 3) * 16;
    const __half* prow = g_p + (size_t)(bh * S + q0 + row) * S;
    const uint32_t ib = (uint32_t)((bh * S + q0 + row) * S);

    float oacc[2][2][4];
    #pragma unroll
    for (int i = 0; i < 2; i++)
        #pragma unroll
        for (int j = 0; j < 2; j++)
            #pragma unroll
            for (int l = 0; l < 4; l++) oacc[i][j][l] = 0.0f;

    for (int c = 0; c < 32; c++) {
        for (int i = tid; i < 512; i += 256) {
            int r = i >> 3, cc = (i & 7) * 8;
            *(uint4*)(sVH + r * PADT + cc) = *(const uint4*)(vhp + (size_t)r * S + c * 64 + cc);
            *(uint4*)(sVL + r * PADT + cc) = *(const uint4*)(vlp + (size_t)r * S + c * 64 + cc);
        }

        const int col0 = c * 64 + cb;
        const float corr = sC[c * 64 + row];

        uint4 pw0 = ((const uint4*)(prow + col0))[0];
        uint4 pw1 = ((const uint4*)(prow + col0))[1];
        const uint32_t pw[8] = {pw0.x, pw0.y, pw0.z, pw0.w, pw1.x, pw1.y, pw1.z, pw1.w};

        uint32_t keepbits = 0xffffffffu;
        if (c & 1) {
            keepbits = 0;
            #pragma unroll
            for (int j = 0; j < 16; j++)
                keepbits |= (threefry_mask_bits(ib + col0 + j) < KEEP_THRESH) ? (1u << j) : 0u;
        }

        uint32_t* dstw = (uint32_t*)(sAT + row * PADT + cb);
        #pragma unroll
        for (int jj = 0; jj < 8; jj++) {
            float2 f = __half22float2(*(const __half2*)&pw[jj]);
            float ta = f.x * corr;
            float tb = f.y * corr;
            ta = ((keepbits >> (jj * 2)) & 1u) ? ta : 0.0f;
            tb = ((keepbits >> (jj * 2 + 1)) & 1u) ? tb : 0.0f;
            dstw[jj] = (uint32_t)__half_as_ushort(__float2half_rn(ta)) |
                       ((uint32_t)__half_as_ushort(__float2half_rn(tb)) << 16);
        }
        __syncthreads();

        #pragma unroll
        for (int ks = 0; ks < 4; ks++) {
            uint32_t a[2][4];
            #pragma unroll
            for (int mt = 0; mt < 2; mt++)
                LDSM_X4(a[mt][0], a[mt][1], a[mt][2], a[mt][3],
                        uAT + (uint32_t)(((arow + mt * 16) * PADT + acol + ks * 16) * 2));
            uint32_t bhf[4], blf[4];
            LDSM_X4(bhf[0], bhf[1], bhf[2], bhf[3],
                    uVH + (uint32_t)((brow * PADT + bcol + ks * 16) * 2));
            LDSM_X4(blf[0], blf[1], blf[2], blf[3],
                    uVL + (uint32_t)((brow * PADT + bcol + ks * 16) * 2));
            #pragma unroll
            for (int mt = 0; mt < 2; mt++)
                #pragma unroll
                for (int nb = 0; nb < 2; nb++) {
                    MMA16816(oacc[mt][nb], a[mt][0], a[mt][1], a[mt][2], a[mt][3],
                             bhf[nb * 2], bhf[nb * 2 + 1]);
                    MMA16816(oacc[mt][nb], a[mt][0], a[mt][1], a[mt][2], a[mt][3],
                             blf[nb * 2], blf[nb * 2 + 1]);
                }
        }
        __syncthreads();
    }

    float* dst = out + ((size_t)bh * S + q0 + qrow0) * 64 + ecol0;
    #pragma unroll
    for (int mt = 0; mt < 2; mt++)
        #pragma unroll
        for (int nb = 0; nb < 2; nb++) {
            *(float2*)(dst + (size_t)(mt * 16 + er) * 64 + nb * 8 + ec) =
                make_float2(oacc[mt][nb][0], oacc[mt][nb][1]);
            *(float2*)(dst + (size_t)(mt * 16 + er + 8) * 64 + nb * 8 + ec) =
                make_float2(oacc[mt][nb][2], oacc[mt][nb][3]);
        }
}
#define PV_SMEM (3 * 64 * PADT * 2 + 32 * 64 * 4)

// ---------------------------------------------------------------------------
extern "C" void kernel_launch(void* const* d_in, const int* in_sizes, int n_in,
                              void* d_out, int out_size) {
    (void)in_sizes; (void)n_in; (void)out_size;
    const float* query = (const float*)d_in[0];
    const float* key   = (const float*)d_in[1];
    const float* value = (const float*)d_in[2];
    const float* Wq    = (const float*)d_in[3];
    const float* bq    = (const float*)d_in[4];
    const float* Wk    = (const float*)d_in[5];
    const float* bk    = (const float*)d_in[6];
    const float* Wv    = (const float*)d_in[7];
    const float* bv    = (const float*)d_in[8];
    float* out = (float*)d_out;

    cudaFuncSetAttribute(proj_kernel,   cudaFuncAttributeMaxDynamicSharedMemorySize, PROJ_SMEM);
    cudaFuncSetAttribute(scores_kernel, cudaFuncAttributeMaxDynamicSharedMemorySize, SC_SMEM);
    cudaFuncSetAttribute(pv_kernel,     cudaFuncAttributeMaxDynamicSharedMemorySize, PV_SMEM);

    dim3 pg(S / 128, BH, 3);
    proj_kernel<<<pg, 256, PROJ_SMEM>>>(query, key, value, Wq, bq, Wk, bk, Wv, bv);

    dim3 sg(S / 64, S / 128, BH);
    scores_kernel<<<sg, 256, SC_SMEM>>>();

    dim3 ag(S / 64, BH);
    pv_kernel<<<ag, 256, PV_SMEM>>>(out);
}

// round 13
// speedup vs baseline: 1.3777x; 1.1768x over previous
#include <cuda_runtime.h>
#include <cuda_fp16.h>
#include <stdint.h>

#define B 4
#define S 2048
#define H 8
#define E 64
#define BH (B*H)
#define PADQ 72
#define PADT 72

// ---------------------------------------------------------------------------
// Device scratch (allocation-free)
// ---------------------------------------------------------------------------
__device__ __half g_qh[(size_t)BH*S*E];   // fp16 of 0.125*Qproj [bh][s][e]
__device__ __half g_kh[(size_t)BH*S*E];   // fp16 of Kproj
__device__ __half g_vh[(size_t)BH*E*S];   // fp16 of Vproj, transposed [bh][e][s]
__device__ __half g_p [(size_t)BH*S*S];   // fp16 p' = exp(s-m_t+ln512), even tiles pre-masked
__device__ float  g_pm[(size_t)BH*16*32*128];
__device__ float  g_pl[(size_t)BH*16*32*128];

// ---------------------------------------------------------------------------
// MMA helpers
// ---------------------------------------------------------------------------
__device__ __forceinline__ uint32_t smem_to_u32(const void* p) {
    uint32_t a;
    asm("{ .reg .u64 t; cvta.to.shared.u64 t, %1; cvt.u32.u64 %0, t; }" : "=r"(a) : "l"(p));
    return a;
}
#define LDSM_X4(R0, R1, R2, R3, ADDR) \
    asm volatile("ldmatrix.sync.aligned.m8n8.x4.shared.b16 {%0,%1,%2,%3}, [%4];" \
                 : "=r"(R0), "=r"(R1), "=r"(R2), "=r"(R3) : "r"(ADDR))
#define MMA16816(C, A0, A1, A2, A3, B0, B1) \
    asm volatile("mma.sync.aligned.m16n8k16.row.col.f32.f16.f16.f32 " \
                 "{%0,%1,%2,%3}, {%4,%5,%6,%7}, {%8,%9}, {%0,%1,%2,%3};" \
                 : "+f"((C)[0]), "+f"((C)[1]), "+f"((C)[2]), "+f"((C)[3]) \
                 : "r"(A0), "r"(A1), "r"(A2), "r"(A3), "r"(B0), "r"(B1))

// ---------------------------------------------------------------------------
// Threefry2x32 (JAX partitionable) — validated rounds 1-12
// ---------------------------------------------------------------------------
__device__ __forceinline__ uint32_t rotl32(uint32_t v, int s) { return __funnelshift_l(v, v, s); }
__device__ __forceinline__ uint32_t threefry_mask_bits(uint32_t idx) {
    const uint32_t ks0 = 0u, ks1 = 42u, ks2 = 0x1BD11BDAu ^ 42u;
    uint32_t x0 = ks0, x1 = idx + ks1;
#define TFR(r) { x0 += x1; x1 = rotl32(x1, r); x1 ^= x0; }
    TFR(13) TFR(15) TFR(26) TFR(6)
    x0 += ks1; x1 += ks2 + 1u;
    TFR(17) TFR(29) TFR(16) TFR(24)
    x0 += ks2; x1 += ks0 + 2u;
    TFR(13) TFR(15) TFR(26) TFR(6)
    x0 += ks0; x1 += ks1 + 3u;
    TFR(17) TFR(29) TFR(16) TFR(24)
    x0 += ks1; x1 += ks2 + 4u;
    TFR(13) TFR(15) TFR(26) TFR(6)
    x0 += ks2; x1 += ks0 + 5u;
#undef TFR
    return x0 ^ x1;
}
#define KEEP_THRESH (7549747u << 9)
#define C512 6.2383246250395075f   // ln(512), cancels in normalization

// ---------------------------------------------------------------------------
// Kernel 1: QKV projection via HMMA (internal hi/lo accuracy; fp16-only outputs)
// ---------------------------------------------------------------------------
#define PW 72
#define SYW 133

__global__ __launch_bounds__(256, 3) void proj_kernel(
    const float* __restrict__ qin, const float* __restrict__ kin, const float* __restrict__ vin,
    const float* __restrict__ Wq, const float* __restrict__ bq,
    const float* __restrict__ Wk, const float* __restrict__ bk,
    const float* __restrict__ Wv, const float* __restrict__ bv)
{
    extern __shared__ char dyn[];
    __half* sWH = (__half*)dyn;               // [64][PW]
    __half* sWL = sWH + 64 * PW;
    __half* sXH = sWL + 64 * PW;              // [128][PW]
    __half* sXL = sXH + 128 * PW;
    float*  sbv = (float*)(sXL + 128 * PW);   // [64]
    uint32_t* sY = (uint32_t*)sXH;            // alias (V epilogue); 64*SYW*4 <= 36864

    const int tid = threadIdx.x;
    const int s0 = blockIdx.x * 128;
    const int bh = blockIdx.y;
    const int m  = blockIdx.z;
    const int b = bh >> 3, h = bh & 7;

    const float* __restrict__ xin  = (m == 0) ? qin : ((m == 1) ? kin : vin);
    const float* __restrict__ W    = (m == 0) ? Wq  : ((m == 1) ? Wk  : Wv);
    const float* __restrict__ bias = (m == 0) ? bq  : ((m == 1) ? bk  : bv);

    for (int i = tid; i < 1024; i += 256) {
        int r = i >> 4, c4 = (i & 15) * 4;
        float4 wv = ((const float4*)W)[i];
        __half h0 = __float2half_rn(wv.x), h1 = __float2half_rn(wv.y);
        __half h2 = __float2half_rn(wv.z), h3 = __float2half_rn(wv.w);
        *(__half2*)(sWH + r * PW + c4)     = __halves2half2(h0, h1);
        *(__half2*)(sWH + r * PW + c4 + 2) = __halves2half2(h2, h3);
        *(__half2*)(sWL + r * PW + c4) = __halves2half2(
            __float2half_rn(wv.x - __half2float(h0)), __float2half_rn(wv.y - __half2float(h1)));
        *(__half2*)(sWL + r * PW + c4 + 2) = __halves2half2(
            __float2half_rn(wv.z - __half2float(h2)), __float2half_rn(wv.w - __half2float(h3)));
    }
    if (tid < 64) sbv[tid] = bias[tid];
    for (int i = tid; i < 2048; i += 256) {
        int r = i >> 4, c4 = (i & 15) * 4;
        float4 xv = ((const float4*)(xin + ((size_t)((b * S + s0 + r) * H + h)) * 64))[i & 15];
        __half h0 = __float2half_rn(xv.x), h1 = __float2half_rn(xv.y);
        __half h2 = __float2half_rn(xv.z), h3 = __float2half_rn(xv.w);
        *(__half2*)(sXH + r * PW + c4)     = __halves2half2(h0, h1);
        *(__half2*)(sXH + r * PW + c4 + 2) = __halves2half2(h2, h3);
        *(__half2*)(sXL + r * PW + c4) = __halves2half2(
            __float2half_rn(xv.x - __half2float(h0)), __float2half_rn(xv.y - __half2float(h1)));
        *(__half2*)(sXL + r * PW + c4 + 2) = __halves2half2(
            __float2half_rn(xv.z - __half2float(h2)), __float2half_rn(xv.w - __half2float(h3)));
    }
    __syncthreads();

    const int w = tid >> 5, lane = tid & 31;
    const int lr = lane & 7, lg = lane >> 3;
    const int er = lane >> 2, ec = (lane & 3) * 2;

    const int arow = w * 16 + lr + (lg & 1) * 8;
    const int acol = (lg >> 1) * 8;
    const int brow = lr + (lg >> 1) * 8;
    const int bcol = (lg & 1) * 8;

    const uint32_t uXH = smem_to_u32(sXH), uXL = smem_to_u32(sXL);
    const uint32_t uWH = smem_to_u32(sWH), uWL = smem_to_u32(sWL);

    float acc[8][4];
    #pragma unroll
    for (int j = 0; j < 8; j++)
        #pragma unroll
        for (int l = 0; l < 4; l++) acc[j][l] = 0.0f;

    #pragma unroll
    for (int ks = 0; ks < 4; ks++) {
        uint32_t aH[4], aL[4], bH[4][4], bL[4][4];
        LDSM_X4(aH[0], aH[1], aH[2], aH[3],
                uXH + (uint32_t)((arow * PW + acol + ks * 16) * 2));
        #pragma unroll
        for (int nbp = 0; nbp < 4; nbp++)
            LDSM_X4(bH[nbp][0], bH[nbp][1], bH[nbp][2], bH[nbp][3],
                    uWH + (uint32_t)(((brow + nbp * 16) * PW + bcol + ks * 16) * 2));
        #pragma unroll
        for (int nb = 0; nb < 8; nb++)
            MMA16816(acc[nb], aH[0], aH[1], aH[2], aH[3],
                     bH[nb >> 1][(nb & 1) * 2], bH[nb >> 1][(nb & 1) * 2 + 1]);
        #pragma unroll
        for (int nbp = 0; nbp < 4; nbp++)
            LDSM_X4(bL[nbp][0], bL[nbp][1], bL[nbp][2], bL[nbp][3],
                    uWL + (uint32_t)(((brow + nbp * 16) * PW + bcol + ks * 16) * 2));
        #pragma unroll
        for (int nb = 0; nb < 8; nb++)
            MMA16816(acc[nb], aH[0], aH[1], aH[2], aH[3],
                     bL[nb >> 1][(nb & 1) * 2], bL[nb >> 1][(nb & 1) * 2 + 1]);
        LDSM_X4(aL[0], aL[1], aL[2], aL[3],
                uXL + (uint32_t)((arow * PW + acol + ks * 16) * 2));
        #pragma unroll
        for (int nb = 0; nb < 8; nb++)
            MMA16816(acc[nb], aL[0], aL[1], aL[2], aL[3],
                     bH[nb >> 1][(nb & 1) * 2], bH[nb >> 1][(nb & 1) * 2 + 1]);
    }

    const float qs = (m == 0) ? 0.125f : 1.0f;
    const int row0 = w * 16 + er;

    if (m < 2) {
        __half* dh = ((m == 0) ? g_qh : g_kh) + ((size_t)bh * S + s0) * 64;
        #pragma unroll
        for (int nb = 0; nb < 8; nb++) {
            const int col = nb * 8 + ec;
            const float b0 = sbv[col], b1 = sbv[col + 1];
            #pragma unroll
            for (int rr = 0; rr < 2; rr++) {
                const int row = row0 + rr * 8;
                float v0 = (acc[nb][rr * 2 + 0] + b0) * qs;
                float v1 = (acc[nb][rr * 2 + 1] + b1) * qs;
                *(__half2*)(dh + (size_t)row * 64 + col) =
                    __halves2half2(__float2half_rn(v0), __float2half_rn(v1));
            }
        }
    } else {
        // V: stage fp16 into sY[f][s] (aliased), then coalesced transpose write
        __syncthreads();
        #pragma unroll
        for (int nb = 0; nb < 8; nb++) {
            const int col = nb * 8 + ec;
            const float b0 = sbv[col], b1 = sbv[col + 1];
            #pragma unroll
            for (int rr = 0; rr < 2; rr++) {
                const int row = row0 + rr * 8;
                sY[col * SYW + row] =
                    (uint32_t)__half_as_ushort(__float2half_rn(acc[nb][rr*2+0] + b0));
                sY[(col + 1) * SYW + row] =
                    (uint32_t)__half_as_ushort(__float2half_rn(acc[nb][rr*2+1] + b1));
            }
        }
        __syncthreads();
        for (int i = tid; i < 1024; i += 256) {
            const int fr = i >> 4, c = i & 15;
            const int sb8 = c * 8;
            uint32_t y[8];
            #pragma unroll
            for (int j = 0; j < 8; j++) y[j] = sY[fr * SYW + sb8 + j];
            uint4 hv;
            hv.x = (y[0] & 0xffffu) | (y[1] << 16);
            hv.y = (y[2] & 0xffffu) | (y[3] << 16);
            hv.z = (y[4] & 0xffffu) | (y[5] << 16);
            hv.w = (y[6] & 0xffffu) | (y[7] << 16);
            *(uint4*)(g_vh + ((size_t)bh * 64 + fr) * S + s0 + sb8) = hv;
        }
    }
}
#define PROJ_SMEM ((2*64*PW + 2*128*PW) * 2 + 64 * 4)

// ---------------------------------------------------------------------------
// Kernel 2: scores (128q x 64k, SINGLE product) -> fp16 p' spill + stats.
// Even-kc tiles: dropout zeroed in-place before store.  occ 4.
// ---------------------------------------------------------------------------
__global__ __launch_bounds__(256, 4) void scores_kernel()
{
    extern __shared__ char smraw[];
    __half* sQ = (__half*)smraw;              // [128][PADQ]
    __half* sK = sQ + 128 * PADQ;             // [64][PADQ]
    float*  sP0 = (float*)(sK + 64 * PADQ);
    float*  sP1 = sP0 + 128;
    float*  sMr = sP1 + 128;

    const int tid = threadIdx.x;
    const int kc = blockIdx.x, qt = blockIdx.y, bh = blockIdx.z;
    const int k0 = kc * 64, q0 = qt * 128;

    const __half* qhp = g_qh + ((size_t)bh * S + q0) * 64;
    const __half* khp = g_kh + ((size_t)bh * S + k0) * 64;

    for (int i = tid; i < 1024; i += 256) {
        int r = i >> 3, c = (i & 7) * 8;
        *(uint4*)(sQ + r * PADQ + c) = *(const uint4*)(qhp + r * 64 + c);
    }
    for (int i = tid; i < 512; i += 256) {
        int r = i >> 3, c = (i & 7) * 8;
        *(uint4*)(sK + r * PADQ + c) = *(const uint4*)(khp + r * 64 + c);
    }
    __syncthreads();

    const int w = tid >> 5, lane = tid & 31;
    const int qrow0 = (w >> 1) * 32, kcol0 = (w & 1) * 32;
    const int lr = lane & 7, lg = lane >> 3;
    const int er = lane >> 2, ec = (lane & 3) * 2;

    const int arow = qrow0 + lr + (lg & 1) * 8;
    const int acol = (lg >> 1) * 8;
    const int brow = kcol0 + lr + (lg >> 1) * 8;
    const int bcol = (lg & 1) * 8;

    const uint32_t uQ = smem_to_u32(sQ), uK = smem_to_u32(sK);

    float acc[2][4][4];
    #pragma unroll
    for (int i = 0; i < 2; i++)
        #pragma unroll
        for (int j = 0; j < 4; j++)
            #pragma unroll
            for (int l = 0; l < 4; l++) acc[i][j][l] = 0.0f;

    #pragma unroll
    for (int ks = 0; ks < 4; ks++) {
        uint32_t a[2][4], bb[2][4];
        #pragma unroll
        for (int mt = 0; mt < 2; mt++)
            LDSM_X4(a[mt][0], a[mt][1], a[mt][2], a[mt][3],
                    uQ + (uint32_t)(((arow + mt * 16) * PADQ + acol + ks * 16) * 2));
        #pragma unroll
        for (int nbp = 0; nbp < 2; nbp++)
            LDSM_X4(bb[nbp][0], bb[nbp][1], bb[nbp][2], bb[nbp][3],
                    uK + (uint32_t)(((brow + nbp * 16) * PADQ + bcol + ks * 16) * 2));
        #pragma unroll
        for (int mt = 0; mt < 2; mt++)
            #pragma unroll
            for (int nb = 0; nb < 4; nb++)
                MMA16816(acc[mt][nb], a[mt][0], a[mt][1], a[mt][2], a[mt][3],
                         bb[nb >> 1][(nb & 1) * 2], bb[nb >> 1][(nb & 1) * 2 + 1]);
    }

    // ---- per-tile row max ----
    float rr2[2][2];
    #pragma unroll
    for (int mt = 0; mt < 2; mt++) {
        float m0 = -1e30f, m1 = -1e30f;
        #pragma unroll
        for (int nb = 0; nb < 4; nb++) {
            m0 = fmaxf(m0, fmaxf(acc[mt][nb][0], acc[mt][nb][1]));
            m1 = fmaxf(m1, fmaxf(acc[mt][nb][2], acc[mt][nb][3]));
        }
        m0 = fmaxf(m0, __shfl_xor_sync(0xffffffffu, m0, 1));
        m0 = fmaxf(m0, __shfl_xor_sync(0xffffffffu, m0, 2));
        m1 = fmaxf(m1, __shfl_xor_sync(0xffffffffu, m1, 1));
        m1 = fmaxf(m1, __shfl_xor_sync(0xffffffffu, m1, 2));
        rr2[mt][0] = m0; rr2[mt][1] = m1;
    }
    float* sP = (w & 1) ? sP1 : sP0;
    if ((lane & 3) == 0) {
        sP[qrow0 + er]      = rr2[0][0];
        sP[qrow0 + er + 8]  = rr2[0][1];
        sP[qrow0 + er + 16] = rr2[1][0];
        sP[qrow0 + er + 24] = rr2[1][1];
    }
    __syncthreads();
    if (tid < 128) sMr[tid] = fmaxf(sP0[tid], sP1[tid]);
    __syncthreads();

    // ---- acc -> p' = exp(s - m_t + ln512); partial l' ----
    float mrow[2][2];
    #pragma unroll
    for (int mt = 0; mt < 2; mt++) {
        mrow[mt][0] = sMr[qrow0 + mt * 16 + er];
        mrow[mt][1] = sMr[qrow0 + mt * 16 + er + 8];
    }
    #pragma unroll
    for (int mt = 0; mt < 2; mt++) {
        float s0 = 0.0f, s1 = 0.0f;
        #pragma unroll
        for (int nb = 0; nb < 4; nb++) {
            acc[mt][nb][0] = __expf(acc[mt][nb][0] - mrow[mt][0] + C512);
            acc[mt][nb][1] = __expf(acc[mt][nb][1] - mrow[mt][0] + C512);
            acc[mt][nb][2] = __expf(acc[mt][nb][2] - mrow[mt][1] + C512);
            acc[mt][nb][3] = __expf(acc[mt][nb][3] - mrow[mt][1] + C512);
            s0 += acc[mt][nb][0] + acc[mt][nb][1];
            s1 += acc[mt][nb][2] + acc[mt][nb][3];
        }
        s0 += __shfl_xor_sync(0xffffffffu, s0, 1);
        s0 += __shfl_xor_sync(0xffffffffu, s0, 2);
        s1 += __shfl_xor_sync(0xffffffffu, s1, 1);
        s1 += __shfl_xor_sync(0xffffffffu, s1, 2);
        rr2[mt][0] = s0; rr2[mt][1] = s1;
    }
    if ((lane & 3) == 0) {
        sP[qrow0 + er]      = rr2[0][0];
        sP[qrow0 + er + 8]  = rr2[0][1];
        sP[qrow0 + er + 16] = rr2[1][0];
        sP[qrow0 + er + 24] = rr2[1][1];
    }
    __syncthreads();
    if (tid < 128) {
        const size_t pidx = (((size_t)bh * 16 + qt) * 32 + kc) * 128 + tid;
        g_pm[pidx] = sMr[tid];
        g_pl[pidx] = sP0[tid] + sP1[tid];
    }

    // ---- dropout for EVEN tiles: zero dropped p' in place ----
    if ((kc & 1) == 0) {
        #pragma unroll
        for (int mt = 0; mt < 2; mt++)
            #pragma unroll
            for (int roff = 0; roff < 2; roff++) {
                const int qg = q0 + qrow0 + mt * 16 + roff * 8 + er;
                const uint32_t idxbase =
                    (uint32_t)(bh * S + qg) * (uint32_t)S + (uint32_t)(k0 + kcol0 + ec);
                #pragma unroll
                for (int nb = 0; nb < 4; nb++) {
                    const uint32_t i0 = idxbase + nb * 8;
                    if (threefry_mask_bits(i0)      >= KEEP_THRESH) acc[mt][nb][roff*2+0] = 0.0f;
                    if (threefry_mask_bits(i0 + 1u) >= KEEP_THRESH) acc[mt][nb][roff*2+1] = 0.0f;
                }
            }
    }

    // ---- store p' fp16 ----
    __half* dst = g_p + ((size_t)bh * S + q0 + qrow0) * S + k0 + kcol0;
    #pragma unroll
    for (int mt = 0; mt < 2; mt++)
        #pragma unroll
        for (int nb = 0; nb < 4; nb++) {
            *(__half2*)(dst + (size_t)(mt * 16 + er) * S + nb * 8 + ec) =
                __floats2half2_rn(acc[mt][nb][0], acc[mt][nb][1]);
            *(__half2*)(dst + (size_t)(mt * 16 + er + 8) * S + nb * 8 + ec) =
                __floats2half2_rn(acc[mt][nb][2], acc[mt][nb][3]);
        }
}
#define SC_SMEM ((128 + 64) * PADQ * 2 + 3 * 128 * 4)

// ---------------------------------------------------------------------------
// Kernel 3: p'-load + corr-scale + odd-tile dropout + fp16 + PV (single V).
// CTA: 64q x one bh; 64-wide chunks; 8 warps = 2(q) x 4(e).  occ 4.
// ---------------------------------------------------------------------------
__global__ __launch_bounds__(256, 4) void pv_kernel(float* __restrict__ out)
{
    extern __shared__ char smraw[];
    __half* sV  = (__half*)smraw;             // [64][PADT]
    __half* sAT = sV + 64 * PADT;             // [64][PADT]
    float*  sC  = (float*)(sAT + 64 * PADT);  // [32][64]

    const int tid = threadIdx.x;
    const int q0 = blockIdx.x * 64, bh = blockIdx.y;

    if (tid < 64) {
        const int qt128 = q0 >> 7;
        const int r128 = (q0 & 127) + tid;
        const size_t pb = (((size_t)bh * 16 + qt128) * 32) * 128 + r128;
        float m = -1e30f;
        #pragma unroll 8
        for (int t = 0; t < 32; t++) m = fmaxf(m, g_pm[pb + t * 128]);
        float l = 0.0f;
        #pragma unroll 8
        for (int t = 0; t < 32; t++) l += g_pl[pb + t * 128] * __expf(g_pm[pb + t * 128] - m);
        const float inv = 1.0f / (0.9f * l);
        #pragma unroll 8
        for (int t = 0; t < 32; t++)
            sC[t * 64 + tid] = __expf(g_pm[pb + t * 128] - m) * inv;
    }
    __syncthreads();

    const int w = tid >> 5, lane = tid & 31;
    const int qrow0 = (w >> 2) * 32, ecol0 = (w & 3) * 16;
    const int lr = lane & 7, lg = lane >> 3;
    const int er = lane >> 2, ec = (lane & 3) * 2;

    const int arow = qrow0 + lr + (lg & 1) * 8;
    const int acol = (lg >> 1) * 8;
    const int brow = ecol0 + lr + (lg >> 1) * 8;
    const int bcol = (lg & 1) * 8;

    const uint32_t uV = smem_to_u32(sV);
    const uint32_t uAT = smem_to_u32(sAT);

    const __half* vhp = g_vh + (size_t)bh * 64 * S;

    const int row = tid >> 2;
    const int cb  = (tid & 3) * 16;
    const __half* prow = g_p + (size_t)(bh * S + q0 + row) * S;
    const uint32_t ib = (uint32_t)((bh * S + q0 + row) * S);

    float oacc[2][2][4];
    #pragma unroll
    for (int i = 0; i < 2; i++)
        #pragma unroll
        for (int j = 0; j < 2; j++)
            #pragma unroll
            for (int l = 0; l < 4; l++) oacc[i][j][l] = 0.0f;

    for (int c = 0; c < 32; c++) {
        for (int i = tid; i < 512; i += 256) {
            int r = i >> 3, cc = (i & 7) * 8;
            *(uint4*)(sV + r * PADT + cc) = *(const uint4*)(vhp + (size_t)r * S + c * 64 + cc);
        }

        const int col0 = c * 64 + cb;
        const float corr = sC[c * 64 + row];

        uint4 pw0 = ((const uint4*)(prow + col0))[0];
        uint4 pw1 = ((const uint4*)(prow + col0))[1];
        const uint32_t pw[8] = {pw0.x, pw0.y, pw0.z, pw0.w, pw1.x, pw1.y, pw1.z, pw1.w};

        uint32_t keepbits = 0xffffffffu;
        if (c & 1) {
            keepbits = 0;
            #pragma unroll
            for (int j = 0; j < 16; j++)
                keepbits |= (threefry_mask_bits(ib + col0 + j) < KEEP_THRESH) ? (1u << j) : 0u;
        }

        uint32_t* dstw = (uint32_t*)(sAT + row * PADT + cb);
        #pragma unroll
        for (int jj = 0; jj < 8; jj++) {
            float2 f = __half22float2(*(const __half2*)&pw[jj]);
            float ta = f.x * corr;
            float tb = f.y * corr;
            ta = ((keepbits >> (jj * 2)) & 1u) ? ta : 0.0f;
            tb = ((keepbits >> (jj * 2 + 1)) & 1u) ? tb : 0.0f;
            dstw[jj] = (uint32_t)__half_as_ushort(__float2half_rn(ta)) |
                       ((uint32_t)__half_as_ushort(__float2half_rn(tb)) << 16);
        }
        __syncthreads();

        #pragma unroll
        for (int ks = 0; ks < 4; ks++) {
            uint32_t a[2][4];
            #pragma unroll
            for (int mt = 0; mt < 2; mt++)
                LDSM_X4(a[mt][0], a[mt][1], a[mt][2], a[mt][3],
                        uAT + (uint32_t)(((arow + mt * 16) * PADT + acol + ks * 16) * 2));
            uint32_t bf[4];
            LDSM_X4(bf[0], bf[1], bf[2], bf[3],
                    uV + (uint32_t)((brow * PADT + bcol + ks * 16) * 2));
            #pragma unroll
            for (int mt = 0; mt < 2; mt++)
                #pragma unroll
                for (int nb = 0; nb < 2; nb++)
                    MMA16816(oacc[mt][nb], a[mt][0], a[mt][1], a[mt][2], a[mt][3],
                             bf[nb * 2], bf[nb * 2 + 1]);
        }
        __syncthreads();
    }

    float* dst = out + ((size_t)bh * S + q0 + qrow0) * 64 + ecol0;
    #pragma unroll
    for (int mt = 0; mt < 2; mt++)
        #pragma unroll
        for (int nb = 0; nb < 2; nb++) {
            *(float2*)(dst + (size_t)(mt * 16 + er) * 64 + nb * 8 + ec) =
                make_float2(oacc[mt][nb][0], oacc[mt][nb][1]);
            *(float2*)(dst + (size_t)(mt * 16 + er + 8) * 64 + nb * 8 + ec) =
                make_float2(oacc[mt][nb][2], oacc[mt][nb][3]);
        }
}
#define PV_SMEM (2 * 64 * PADT * 2 + 32 * 64 * 4)

// ---------------------------------------------------------------------------
extern "C" void kernel_launch(void* const* d_in, const int* in_sizes, int n_in,
                              void* d_out, int out_size) {
    (void)in_sizes; (void)n_in; (void)out_size;
    const float* query = (const float*)d_in[0];
    const float* key   = (const float*)d_in[1];
    const float* value = (const float*)d_in[2];
    const float* Wq    = (const float*)d_in[3];
    const float* bq    = (const float*)d_in[4];
    const float* Wk    = (const float*)d_in[5];
    const float* bk    = (const float*)d_in[6];
    const float* Wv    = (const float*)d_in[7];
    const float* bv    = (const float*)d_in[8];
    float* out = (float*)d_out;

    cudaFuncSetAttribute(proj_kernel,   cudaFuncAttributeMaxDynamicSharedMemorySize, PROJ_SMEM);
    cudaFuncSetAttribute(scores_kernel, cudaFuncAttributeMaxDynamicSharedMemorySize, SC_SMEM);
    cudaFuncSetAttribute(pv_kernel,     cudaFuncAttributeMaxDynamicSharedMemorySize, PV_SMEM);

    dim3 pg(S / 128, BH, 3);
    proj_kernel<<<pg, 256, PROJ_SMEM>>>(query, key, value, Wq, bq, Wk, bk, Wv, bv);

    dim3 sg(S / 64, S / 128, BH);
    scores_kernel<<<sg, 256, SC_SMEM>>>();

    dim3 ag(S / 64, BH);
    pv_kernel<<<ag, 256, PV_SMEM>>>(out);
}

// round 14
// speedup vs baseline: 1.6822x; 1.2210x over previous
#include <cuda_runtime.h>
#include <cuda_fp16.h>
#include <stdint.h>

#define B 4
#define S 2048
#define H 8
#define E 64
#define BH (B*H)
#define FQ 72   // smem row stride (halves)

// ---------------------------------------------------------------------------
// Device scratch (allocation-free)
// ---------------------------------------------------------------------------
__device__ __half g_qh[(size_t)BH*S*E];   // fp16 of 0.125*Qproj [bh][s][e]
__device__ __half g_kh[(size_t)BH*S*E];   // fp16 of Kproj
__device__ __half g_vh[(size_t)BH*E*S];   // fp16 of Vproj, transposed [bh][e][s]

// ---------------------------------------------------------------------------
// MMA helpers
// ---------------------------------------------------------------------------
__device__ __forceinline__ uint32_t smem_to_u32(const void* p) {
    uint32_t a;
    asm("{ .reg .u64 t; cvta.to.shared.u64 t, %1; cvt.u32.u64 %0, t; }" : "=r"(a) : "l"(p));
    return a;
}
#define LDSM_X4(R0, R1, R2, R3, ADDR) \
    asm volatile("ldmatrix.sync.aligned.m8n8.x4.shared.b16 {%0,%1,%2,%3}, [%4];" \
                 : "=r"(R0), "=r"(R1), "=r"(R2), "=r"(R3) : "r"(ADDR))
#define MMA16816(C, A0, A1, A2, A3, B0, B1) \
    asm volatile("mma.sync.aligned.m16n8k16.row.col.f32.f16.f16.f32 " \
                 "{%0,%1,%2,%3}, {%4,%5,%6,%7}, {%8,%9}, {%0,%1,%2,%3};" \
                 : "+f"((C)[0]), "+f"((C)[1]), "+f"((C)[2]), "+f"((C)[3]) \
                 : "r"(A0), "r"(A1), "r"(A2), "r"(A3), "r"(B0), "r"(B1))

// ---------------------------------------------------------------------------
// Threefry2x32 (JAX partitionable) — validated rounds 1-13
// ---------------------------------------------------------------------------
__device__ __forceinline__ uint32_t rotl32(uint32_t v, int s) { return __funnelshift_l(v, v, s); }
__device__ __forceinline__ uint32_t threefry_mask_bits(uint32_t idx) {
    const uint32_t ks0 = 0u, ks1 = 42u, ks2 = 0x1BD11BDAu ^ 42u;
    uint32_t x0 = ks0, x1 = idx + ks1;
#define TFR(r) { x0 += x1; x1 = rotl32(x1, r); x1 ^= x0; }
    TFR(13) TFR(15) TFR(26) TFR(6)
    x0 += ks1; x1 += ks2 + 1u;
    TFR(17) TFR(29) TFR(16) TFR(24)
    x0 += ks2; x1 += ks0 + 2u;
    TFR(13) TFR(15) TFR(26) TFR(6)
    x0 += ks0; x1 += ks1 + 3u;
    TFR(17) TFR(29) TFR(16) TFR(24)
    x0 += ks1; x1 += ks2 + 4u;
    TFR(13) TFR(15) TFR(26) TFR(6)
    x0 += ks2; x1 += ks0 + 5u;
#undef TFR
    return x0 ^ x1;
}
#define KEEP_THRESH (7549747u << 9)
#define C512 6.2383246250395075f   // ln(512): fp16 range guard, cancels in normalization

// ---------------------------------------------------------------------------
// Kernel 1: QKV projection via HMMA (round-13 version, measured ~41us)
// ---------------------------------------------------------------------------
#define PW 72
#define SYW 133

__global__ __launch_bounds__(256, 3) void proj_kernel(
    const float* __restrict__ qin, const float* __restrict__ kin, const float* __restrict__ vin,
    const float* __restrict__ Wq, const float* __restrict__ bq,
    const float* __restrict__ Wk, const float* __restrict__ bk,
    const float* __restrict__ Wv, const float* __restrict__ bv)
{
    extern __shared__ char dyn[];
    __half* sWH = (__half*)dyn;
    __half* sWL = sWH + 64 * PW;
    __half* sXH = sWL + 64 * PW;
    __half* sXL = sXH + 128 * PW;
    float*  sbv = (float*)(sXL + 128 * PW);
    uint32_t* sY = (uint32_t*)sXH;

    const int tid = threadIdx.x;
    const int s0 = blockIdx.x * 128;
    const int bh = blockIdx.y;
    const int m  = blockIdx.z;
    const int b = bh >> 3, h = bh & 7;

    const float* __restrict__ xin  = (m == 0) ? qin : ((m == 1) ? kin : vin);
    const float* __restrict__ W    = (m == 0) ? Wq  : ((m == 1) ? Wk  : Wv);
    const float* __restrict__ bias = (m == 0) ? bq  : ((m == 1) ? bk  : bv);

    for (int i = tid; i < 1024; i += 256) {
        int r = i >> 4, c4 = (i & 15) * 4;
        float4 wv = ((const float4*)W)[i];
        __half h0 = __float2half_rn(wv.x), h1 = __float2half_rn(wv.y);
        __half h2 = __float2half_rn(wv.z), h3 = __float2half_rn(wv.w);
        *(__half2*)(sWH + r * PW + c4)     = __halves2half2(h0, h1);
        *(__half2*)(sWH + r * PW + c4 + 2) = __halves2half2(h2, h3);
        *(__half2*)(sWL + r * PW + c4) = __halves2half2(
            __float2half_rn(wv.x - __half2float(h0)), __float2half_rn(wv.y - __half2float(h1)));
        *(__half2*)(sWL + r * PW + c4 + 2) = __halves2half2(
            __float2half_rn(wv.z - __half2float(h2)), __float2half_rn(wv.w - __half2float(h3)));
    }
    if (tid < 64) sbv[tid] = bias[tid];
    for (int i = tid; i < 2048; i += 256) {
        int r = i >> 4, c4 = (i & 15) * 4;
        float4 xv = ((const float4*)(xin + ((size_t)((b * S + s0 + r) * H + h)) * 64))[i & 15];
        __half h0 = __float2half_rn(xv.x), h1 = __float2half_rn(xv.y);
        __half h2 = __float2half_rn(xv.z), h3 = __float2half_rn(xv.w);
        *(__half2*)(sXH + r * PW + c4)     = __halves2half2(h0, h1);
        *(__half2*)(sXH + r * PW + c4 + 2) = __halves2half2(h2, h3);
        *(__half2*)(sXL + r * PW + c4) = __halves2half2(
            __float2half_rn(xv.x - __half2float(h0)), __float2half_rn(xv.y - __half2float(h1)));
        *(__half2*)(sXL + r * PW + c4 + 2) = __halves2half2(
            __float2half_rn(xv.z - __half2float(h2)), __float2half_rn(xv.w - __half2float(h3)));
    }
    __syncthreads();

    const int w = tid >> 5, lane = tid & 31;
    const int lr = lane & 7, lg = lane >> 3;
    const int er = lane >> 2, ec = (lane & 3) * 2;

    const int arow = w * 16 + lr + (lg & 1) * 8;
    const int acol = (lg >> 1) * 8;
    const int brow = lr + (lg >> 1) * 8;
    const int bcol = (lg & 1) * 8;

    const uint32_t uXH = smem_to_u32(sXH), uXL = smem_to_u32(sXL);
    const uint32_t uWH = smem_to_u32(sWH), uWL = smem_to_u32(sWL);

    float acc[8][4];
    #pragma unroll
    for (int j = 0; j < 8; j++)
        #pragma unroll
        for (int l = 0; l < 4; l++) acc[j][l] = 0.0f;

    #pragma unroll
    for (int ks = 0; ks < 4; ks++) {
        uint32_t aH[4], aL[4], bH[4][4], bL[4][4];
        LDSM_X4(aH[0], aH[1], aH[2], aH[3],
                uXH + (uint32_t)((arow * PW + acol + ks * 16) * 2));
        #pragma unroll
        for (int nbp = 0; nbp < 4; nbp++)
            LDSM_X4(bH[nbp][0], bH[nbp][1], bH[nbp][2], bH[nbp][3],
                    uWH + (uint32_t)(((brow + nbp * 16) * PW + bcol + ks * 16) * 2));
        #pragma unroll
        for (int nb = 0; nb < 8; nb++)
            MMA16816(acc[nb], aH[0], aH[1], aH[2], aH[3],
                     bH[nb >> 1][(nb & 1) * 2], bH[nb >> 1][(nb & 1) * 2 + 1]);
        #pragma unroll
        for (int nbp = 0; nbp < 4; nbp++)
            LDSM_X4(bL[nbp][0], bL[nbp][1], bL[nbp][2], bL[nbp][3],
                    uWL + (uint32_t)(((brow + nbp * 16) * PW + bcol + ks * 16) * 2));
        #pragma unroll
        for (int nb = 0; nb < 8; nb++)
            MMA16816(acc[nb], aH[0], aH[1], aH[2], aH[3],
                     bL[nb >> 1][(nb & 1) * 2], bL[nb >> 1][(nb & 1) * 2 + 1]);
        LDSM_X4(aL[0], aL[1], aL[2], aL[3],
                uXL + (uint32_t)((arow * PW + acol + ks * 16) * 2));
        #pragma unroll
        for (int nb = 0; nb < 8; nb++)
            MMA16816(acc[nb], aL[0], aL[1], aL[2], aL[3],
                     bH[nb >> 1][(nb & 1) * 2], bH[nb >> 1][(nb & 1) * 2 + 1]);
    }

    const float qs = (m == 0) ? 0.125f : 1.0f;
    const int row0 = w * 16 + er;

    if (m < 2) {
        __half* dh = ((m == 0) ? g_qh : g_kh) + ((size_t)bh * S + s0) * 64;
        #pragma unroll
        for (int nb = 0; nb < 8; nb++) {
            const int col = nb * 8 + ec;
            const float b0 = sbv[col], b1 = sbv[col + 1];
            #pragma unroll
            for (int rr = 0; rr < 2; rr++) {
                const int row = row0 + rr * 8;
                float v0 = (acc[nb][rr * 2 + 0] + b0) * qs;
                float v1 = (acc[nb][rr * 2 + 1] + b1) * qs;
                *(__half2*)(dh + (size_t)row * 64 + col) =
                    __halves2half2(__float2half_rn(v0), __float2half_rn(v1));
            }
        }
    } else {
        __syncthreads();
        #pragma unroll
        for (int nb = 0; nb < 8; nb++) {
            const int col = nb * 8 + ec;
            const float b0 = sbv[col], b1 = sbv[col + 1];
            #pragma unroll
            for (int rr = 0; rr < 2; rr++) {
                const int row = row0 + rr * 8;
                sY[col * SYW + row] =
                    (uint32_t)__half_as_ushort(__float2half_rn(acc[nb][rr*2+0] + b0));
                sY[(col + 1) * SYW + row] =
                    (uint32_t)__half_as_ushort(__float2half_rn(acc[nb][rr*2+1] + b1));
            }
        }
        __syncthreads();
        for (int i = tid; i < 1024; i += 256) {
            const int fr = i >> 4, c = i & 15;
            const int sb8 = c * 8;
            uint32_t y[8];
            #pragma unroll
            for (int j = 0; j < 8; j++) y[j] = sY[fr * SYW + sb8 + j];
            uint4 hv;
            hv.x = (y[0] & 0xffffu) | (y[1] << 16);
            hv.y = (y[2] & 0xffffu) | (y[3] << 16);
            hv.z = (y[4] & 0xffffu) | (y[5] << 16);
            hv.w = (y[6] & 0xffffu) | (y[7] << 16);
            *(uint4*)(g_vh + ((size_t)bh * 64 + fr) * S + s0 + sb8) = hv;
        }
    }
}
#define PROJ_SMEM ((2*64*PW + 2*128*PW) * 2 + 64 * 4)

// ---------------------------------------------------------------------------
// Kernel 2: fused flash attention (online softmax + dropout + PV).
// CTA: 64 q-rows x one bh; 32 chunks of 64 k.  8 warps = 2(q) x 4(k|e).
// ---------------------------------------------------------------------------
__global__ __launch_bounds__(256, 3) void flash_kernel(float* __restrict__ out)
{
    extern __shared__ char smraw[];
    __half* sQ  = (__half*)smraw;             // [64][FQ]
    __half* sK  = sQ + 64 * FQ;               // [64][FQ]
    __half* sV  = sK + 64 * FQ;               // [64][FQ]
    __half* sAT = sV + 64 * FQ;               // [64][FQ]
    float*  sPm = (float*)(sAT + 64 * FQ);    // [4][64] max partials
    float*  sPs = sPm + 256;                  // [4][64] sum partials
    float*  sM  = sPs + 256;                  // [64] running max
    float*  sL  = sM + 64;                    // [64] running sum
    float*  sRe = sL + 64;                    // [64] rescale factor
    float*  sIv = sRe + 64;                   // [64] final 1/(0.9 l)

    const int tid = threadIdx.x;
    const int q0 = blockIdx.x * 64, bh = blockIdx.y;

    const __half* qhp = g_qh + ((size_t)bh * S + q0) * 64;
    const __half* khp = g_kh + (size_t)bh * S * 64;
    const __half* vhp = g_vh + (size_t)bh * 64 * S;

    for (int i = tid; i < 512; i += 256) {
        int r = i >> 3, cc = (i & 7) * 8;
        *(uint4*)(sQ + r * FQ + cc) = *(const uint4*)(qhp + r * 64 + cc);
    }
    if (tid < 64) { sM[tid] = -1e30f; sL[tid] = 0.0f; }

    const int w = tid >> 5, lane = tid & 31;
    const int qrow0 = (w >> 2) * 32;          // shared by score & PV layouts
    const int kcol0 = (w & 3) * 16;           // score: k quarter
    const int ecol0 = (w & 3) * 16;           // PV: e quarter
    const int lr = lane & 7, lg = lane >> 3;
    const int er = lane >> 2, ec = (lane & 3) * 2;

    const int arow = qrow0 + lr + (lg & 1) * 8;   // A rows (Q / attn)
    const int acol = (lg >> 1) * 8;
    const int sbrow = kcol0 + lr + (lg >> 1) * 8; // score B rows (K)
    const int pbrow = ecol0 + lr + (lg >> 1) * 8; // PV B rows (V: e)
    const int bcol = (lg & 1) * 8;

    const uint32_t uQ = smem_to_u32(sQ), uK = smem_to_u32(sK);
    const uint32_t uV = smem_to_u32(sV), uAT = smem_to_u32(sAT);

    // row indices this thread owns (same in both layouts)
    const int R0 = qrow0 + er, R1 = R0 + 8, R2 = R0 + 16, R3 = R0 + 24;
    const uint32_t ibase = (uint32_t)(bh * S + q0) * (uint32_t)S;

    float oacc[2][2][4];
    #pragma unroll
    for (int i = 0; i < 2; i++)
        #pragma unroll
        for (int j = 0; j < 2; j++)
            #pragma unroll
            for (int l = 0; l < 4; l++) oacc[i][j][l] = 0.0f;

    for (int c = 0; c < 32; c++) {
        __syncthreads();   // S1: prev chunk's MMA reads of sK/sV/sAT complete
        for (int i = tid; i < 512; i += 256) {
            int r = i >> 3, cc = (i & 7) * 8;
            *(uint4*)(sK + r * FQ + cc) = *(const uint4*)(khp + (size_t)(c * 64 + r) * 64 + cc);
            *(uint4*)(sV + r * FQ + cc) = *(const uint4*)(vhp + (size_t)r * S + c * 64 + cc);
        }
        __syncthreads();   // S2

        // ---- score MMA: acc[mt][nb][l], warp tile 32q x 16k ----
        float acc[2][2][4];
        #pragma unroll
        for (int i = 0; i < 2; i++)
            #pragma unroll
            for (int j = 0; j < 2; j++)
                #pragma unroll
                for (int l = 0; l < 4; l++) acc[i][j][l] = 0.0f;
        #pragma unroll
        for (int ks = 0; ks < 4; ks++) {
            uint32_t a[2][4], bb[4];
            #pragma unroll
            for (int mt = 0; mt < 2; mt++)
                LDSM_X4(a[mt][0], a[mt][1], a[mt][2], a[mt][3],
                        uQ + (uint32_t)(((arow + mt * 16) * FQ + acol + ks * 16) * 2));
            LDSM_X4(bb[0], bb[1], bb[2], bb[3],
                    uK + (uint32_t)((sbrow * FQ + bcol + ks * 16) * 2));
            #pragma unroll
            for (int mt = 0; mt < 2; mt++)
                #pragma unroll
                for (int nb = 0; nb < 2; nb++)
                    MMA16816(acc[mt][nb], a[mt][0], a[mt][1], a[mt][2], a[mt][3],
                             bb[nb * 2], bb[nb * 2 + 1]);
        }

        // ---- chunk row max -> sPm[w&3] ----
        #pragma unroll
        for (int mt = 0; mt < 2; mt++) {
            float m0 = fmaxf(fmaxf(acc[mt][0][0], acc[mt][0][1]),
                             fmaxf(acc[mt][1][0], acc[mt][1][1]));
            float m1 = fmaxf(fmaxf(acc[mt][0][2], acc[mt][0][3]),
                             fmaxf(acc[mt][1][2], acc[mt][1][3]));
            m0 = fmaxf(m0, __shfl_xor_sync(0xffffffffu, m0, 1));
            m0 = fmaxf(m0, __shfl_xor_sync(0xffffffffu, m0, 2));
            m1 = fmaxf(m1, __shfl_xor_sync(0xffffffffu, m1, 1));
            m1 = fmaxf(m1, __shfl_xor_sync(0xffffffffu, m1, 2));
            if ((lane & 3) == 0) {
                sPm[(w & 3) * 64 + qrow0 + mt * 16 + er] = m0;
                sPm[(w & 3) * 64 + qrow0 + mt * 16 + er + 8] = m1;
            }
        }
        __syncthreads();   // S3
        if (tid < 64) {
            float cm = fmaxf(fmaxf(sPm[tid], sPm[64 + tid]),
                             fmaxf(sPm[128 + tid], sPm[192 + tid]));
            float mo = sM[tid];
            float mn = fmaxf(mo, cm);
            sRe[tid] = __expf(mo - mn);
            sM[tid] = mn;
        }
        __syncthreads();   // S4

        // ---- rescale oacc ----
        {
            const float r0 = sRe[R0], r1 = sRe[R1], r2 = sRe[R2], r3 = sRe[R3];
            #pragma unroll
            for (int nb = 0; nb < 2; nb++) {
                oacc[0][nb][0] *= r0; oacc[0][nb][1] *= r0;
                oacc[0][nb][2] *= r1; oacc[0][nb][3] *= r1;
                oacc[1][nb][0] *= r2; oacc[1][nb][1] *= r2;
                oacc[1][nb][2] *= r3; oacc[1][nb][3] *= r3;
            }
        }

        // ---- exp + sums + threefry mask + fp16 -> sAT ----
        {
            const float mv0 = sM[R0], mv1 = sM[R1], mv2 = sM[R2], mv3 = sM[R3];
            float s0 = 0.0f, s1 = 0.0f, s2 = 0.0f, s3 = 0.0f;
            #pragma unroll
            for (int nb = 0; nb < 2; nb++) {
                acc[0][nb][0] = __expf(acc[0][nb][0] - mv0 + C512);
                acc[0][nb][1] = __expf(acc[0][nb][1] - mv0 + C512);
                acc[0][nb][2] = __expf(acc[0][nb][2] - mv1 + C512);
                acc[0][nb][3] = __expf(acc[0][nb][3] - mv1 + C512);
                acc[1][nb][0] = __expf(acc[1][nb][0] - mv2 + C512);
                acc[1][nb][1] = __expf(acc[1][nb][1] - mv2 + C512);
                acc[1][nb][2] = __expf(acc[1][nb][2] - mv3 + C512);
                acc[1][nb][3] = __expf(acc[1][nb][3] - mv3 + C512);
                s0 += acc[0][nb][0] + acc[0][nb][1];
                s1 += acc[0][nb][2] + acc[0][nb][3];
                s2 += acc[1][nb][0] + acc[1][nb][1];
                s3 += acc[1][nb][2] + acc[1][nb][3];
            }
            s0 += __shfl_xor_sync(0xffffffffu, s0, 1);
            s0 += __shfl_xor_sync(0xffffffffu, s0, 2);
            s1 += __shfl_xor_sync(0xffffffffu, s1, 1);
            s1 += __shfl_xor_sync(0xffffffffu, s1, 2);
            s2 += __shfl_xor_sync(0xffffffffu, s2, 1);
            s2 += __shfl_xor_sync(0xffffffffu, s2, 2);
            s3 += __shfl_xor_sync(0xffffffffu, s3, 1);
            s3 += __shfl_xor_sync(0xffffffffu, s3, 2);
            if ((lane & 3) == 0) {
                sPs[(w & 3) * 64 + R0] = s0;
                sPs[(w & 3) * 64 + R1] = s1;
                sPs[(w & 3) * 64 + R2] = s2;
                sPs[(w & 3) * 64 + R3] = s3;
            }

            // dropout (all tiles) + fp16 store to sAT
            const uint32_t kg0 = (uint32_t)(c * 64 + kcol0 + ec);
            #pragma unroll
            for (int mt = 0; mt < 2; mt++)
                #pragma unroll
                for (int roff = 0; roff < 2; roff++) {
                    const int rloc = qrow0 + mt * 16 + roff * 8 + er;
                    const uint32_t idxb = ibase + (uint32_t)rloc * (uint32_t)S + kg0;
                    #pragma unroll
                    for (int nb = 0; nb < 2; nb++) {
                        const uint32_t i0 = idxb + nb * 8;
                        float va = acc[mt][nb][roff * 2 + 0];
                        float vb = acc[mt][nb][roff * 2 + 1];
                        if (threefry_mask_bits(i0)      >= KEEP_THRESH) va = 0.0f;
                        if (threefry_mask_bits(i0 + 1u) >= KEEP_THRESH) vb = 0.0f;
                        *(__half2*)(sAT + rloc * FQ + kcol0 + nb * 8 + ec) =
                            __floats2half2_rn(va, vb);
                    }
                }
        }
        __syncthreads();   // S5
        if (tid < 64)
            sL[tid] = sL[tid] * sRe[tid] +
                      (sPs[tid] + sPs[64 + tid] + sPs[128 + tid] + sPs[192 + tid]);

        // ---- PV MMA: oacc += attn(64x64) @ V(64k x 16e per warp) ----
        #pragma unroll
        for (int ks = 0; ks < 4; ks++) {
            uint32_t a[2][4], bf[4];
            #pragma unroll
            for (int mt = 0; mt < 2; mt++)
                LDSM_X4(a[mt][0], a[mt][1], a[mt][2], a[mt][3],
                        uAT + (uint32_t)(((arow + mt * 16) * FQ + acol + ks * 16) * 2));
            LDSM_X4(bf[0], bf[1], bf[2], bf[3],
                    uV + (uint32_t)((pbrow * FQ + bcol + ks * 16) * 2));
            #pragma unroll
            for (int mt = 0; mt < 2; mt++)
                #pragma unroll
                for (int nb = 0; nb < 2; nb++)
                    MMA16816(oacc[mt][nb], a[mt][0], a[mt][1], a[mt][2], a[mt][3],
                             bf[nb * 2], bf[nb * 2 + 1]);
        }
    }

    __syncthreads();
    if (tid < 64) sIv[tid] = 1.0f / (0.9f * sL[tid]);
    __syncthreads();

    // epilogue: out = oacc * (1/(0.9 l))
    const float i0 = sIv[R0], i1 = sIv[R1], i2 = sIv[R2], i3 = sIv[R3];
    float* dst = out + ((size_t)bh * S + q0 + qrow0) * 64 + ecol0;
    #pragma unroll
    for (int nb = 0; nb < 2; nb++) {
        *(float2*)(dst + (size_t)(er) * 64 + nb * 8 + ec) =
            make_float2(oacc[0][nb][0] * i0, oacc[0][nb][1] * i0);
        *(float2*)(dst + (size_t)(er + 8) * 64 + nb * 8 + ec) =
            make_float2(oacc[0][nb][2] * i1, oacc[0][nb][3] * i1);
        *(float2*)(dst + (size_t)(16 + er) * 64 + nb * 8 + ec) =
            make_float2(oacc[1][nb][0] * i2, oacc[1][nb][1] * i2);
        *(float2*)(dst + (size_t)(16 + er + 8) * 64 + nb * 8 + ec) =
            make_float2(oacc[1][nb][2] * i3, oacc[1][nb][3] * i3);
    }
}
#define FL_SMEM (4 * 64 * FQ * 2 + (256 + 256 + 64 * 4) * 4)

// ---------------------------------------------------------------------------
extern "C" void kernel_launch(void* const* d_in, const int* in_sizes, int n_in,
                              void* d_out, int out_size) {
    (void)in_sizes; (void)n_in; (void)out_size;
    const float* query = (const float*)d_in[0];
    const float* key   = (const float*)d_in[1];
    const float* value = (const float*)d_in[2];
    const float* Wq    = (const float*)d_in[3];
    const float* bq    = (const float*)d_in[4];
    const float* Wk    = (const float*)d_in[5];
    const float* bk    = (const float*)d_in[6];
    const float* Wv    = (const float*)d_in[7];
    const float* bv    = (const float*)d_in[8];
    float* out = (float*)d_out;

    cudaFuncSetAttribute(proj_kernel,  cudaFuncAttributeMaxDynamicSharedMemorySize, PROJ_SMEM);
    cudaFuncSetAttribute(flash_kernel, cudaFuncAttributeMaxDynamicSharedMemorySize, FL_SMEM);

    dim3 pg(S / 128, BH, 3);
    proj_kernel<<<pg, 256, PROJ_SMEM>>>(query, key, value, Wq, bq, Wk, bk, Wv, bv);

    dim3 fg(S / 64, BH);
    flash_kernel<<<fg, 256, FL_SMEM>>>(out);
}